// round 7
// baseline (speedup 1.0000x reference)
#include <cuda_runtime.h>
#include <math.h>

#define Bn 128
#define Wn 64
#define En 256
#define Dn 256

#define NBLK 128
#define NTHR 512

// __device__ scratch (allocation-free rule)
__device__ float g_P[Bn * Wn * En];          // P[b,w,e] (8 MB)
__device__ float g_HC[Bn * 2 * Dn];          // [b][0:256]=h, [b][256:512]=c
__device__ float g_Sp[4][Bn * En];           // S K-partials
__device__ float g_Gp[2][Bn * 4 * Dn];       // Ghh K-partials
__device__ volatile unsigned g_bar_gen;
__device__ unsigned g_bar_cnt;

// ---------------------------------------------------------------------------
__device__ __forceinline__ float tanh_fast(float x) {
    float y;
    asm("tanh.approx.f32 %0, %1;" : "=f"(y) : "f"(x));
    return y;
}
__device__ __forceinline__ unsigned long long pack2(float x, float y) {
    unsigned long long r;
    asm("mov.b64 %0, {%1, %2};" : "=l"(r) : "f"(x), "f"(y));
    return r;
}
__device__ __forceinline__ unsigned long long fma2(unsigned long long a,
                                                   unsigned long long b,
                                                   unsigned long long c) {
    unsigned long long d;
    asm("fma.rn.f32x2 %0, %1, %2, %3;" : "=l"(d) : "l"(a), "l"(b), "l"(c));
    return d;
}
__device__ __forceinline__ float2 unpack2(unsigned long long v) {
    float lo, hi;
    asm("mov.b64 {%0, %1}, %2;" : "=f"(lo), "=f"(hi) : "l"(v));
    return make_float2(lo, hi);
}

__device__ __forceinline__ void grid_barrier() {
    __syncthreads();
    if (threadIdx.x == 0) {
        __threadfence();
        unsigned gen = g_bar_gen;
        if (atomicAdd(&g_bar_cnt, 1u) == NBLK - 1u) {
            atomicExch(&g_bar_cnt, 0u);
            __threadfence();
            g_bar_gen = gen + 1u;
        } else {
            while (g_bar_gen == gen) { }
            __threadfence();
        }
    }
    __syncthreads();
}

// ---------------------------------------------------------------------------
// Stage 64 rows x 128 k of X (row-major ldx) into Xst[k][r] (stride 64).
// 512 threads: each thread 4 float4.
__device__ __forceinline__ void stage64x128(const float* __restrict__ Xp, int ldx,
                                            float* __restrict__ Xst) {
    const int tid = threadIdx.x;
    const int r  = tid & 63;
    const int kg = tid >> 6;                  // 0..7
#pragma unroll
    for (int q = 0; q < 4; q++) {
        int k4 = (kg + q * 8) << 2;
        float4 v = *(const float4*)(Xp + r * ldx + k4);
        Xst[(k4 + 0) * 64 + r] = v.x;
        Xst[(k4 + 1) * 64 + r] = v.y;
        Xst[(k4 + 2) * 64 + r] = v.z;
        Xst[(k4 + 3) * 64 + r] = v.w;
    }
}

// 64x64 x 128k accumulate, 512 threads, 2x4 micro-tile (packed pairs).
__device__ __forceinline__ void mma128(const float* __restrict__ Ast,
                                       const float* __restrict__ Bst,
                                       unsigned long long acc[2][2]) {
    const int ty = threadIdx.x >> 4;          // 0..31 -> rows ty*2..
    const int tx = threadIdx.x & 15;          // 0..15 -> cols tx*4..
#pragma unroll 8
    for (int k = 0; k < 128; k++) {
        float2 a = *(const float2*)&Ast[k * 64 + ty * 2];
        ulonglong2 bv = *(const ulonglong2*)&Bst[k * 64 + tx * 4];
        unsigned long long a0 = pack2(a.x, a.x);
        unsigned long long a1 = pack2(a.y, a.y);
        acc[0][0] = fma2(a0, bv.x, acc[0][0]); acc[0][1] = fma2(a0, bv.y, acc[0][1]);
        acc[1][0] = fma2(a1, bv.x, acc[1][0]); acc[1][1] = fma2(a1, bv.y, acc[1][1]);
    }
}

__device__ __forceinline__ void epilogue(unsigned long long acc[2][2],
                                         float* __restrict__ Cptr, int ldc,
                                         const float* __restrict__ bias) {
    const int ty = threadIdx.x >> 4, tx = threadIdx.x & 15;
    float4 bb = make_float4(0.f, 0.f, 0.f, 0.f);
    if (bias) bb = *(const float4*)&bias[tx * 4];
#pragma unroll
    for (int i = 0; i < 2; i++) {
        float2 lo = unpack2(acc[i][0]);
        float2 hi = unpack2(acc[i][1]);
        float4 o;
        o.x = lo.x + bb.x; o.y = lo.y + bb.y;
        o.z = hi.x + bb.z; o.w = hi.y + bb.w;
        *(float4*)&Cptr[(ty * 2 + i) * ldc + tx * 4] = o;
    }
}

// Full tile GEMM (stages both operands) for the precompute.
__device__ __forceinline__ void gemm64_full(
    const float* __restrict__ Aptr, int lda,
    const float* __restrict__ Bptr, int ldb,
    float* __restrict__ Cptr, int ldc,
    int nchunk, const float* __restrict__ bias,
    float* __restrict__ Ast, float* __restrict__ Bst)
{
    unsigned long long acc[2][2];
    acc[0][0] = acc[0][1] = acc[1][0] = acc[1][1] = 0ull;
    for (int c = 0; c < nchunk; c++) {
        stage64x128(Aptr + c * 128, lda, Ast);
        stage64x128(Bptr + c * 128, ldb, Bst);
        __syncthreads();
        mma128(Ast, Bst, acc);
        __syncthreads();
    }
    epilogue(acc, Cptr, ldc, bias);
}

// ---------------------------------------------------------------------------
__global__ __launch_bounds__(NTHR, 1)
void decoder_persistent(
    const float* __restrict__ enc,  const float* __restrict__ yh,
    const float* __restrict__ w1,   const float* __restrict__ b1,
    const float* __restrict__ w2,   const float* __restrict__ b2,
    const float* __restrict__ wih,  const float* __restrict__ whh,
    const float* __restrict__ bih,  const float* __restrict__ bhh,
    const float* __restrict__ fcw,  const float* __restrict__ fcb,
    const float* __restrict__ fcfw, const float* __restrict__ fcfb,
    float* __restrict__ out)
{
    extern __shared__ float sm[];
    float* sEnc = sm;            // 16384
    float* sP   = sm + 16384;    // 16384
    float* sW2  = sm + 32768;    // 256
    float* scr  = sm + 33024;    // 16384: [Ast 8192 | Bw 8192]
    float* Ast  = scr;
    float* Bw   = scr + 8192;    // persistent per-block weight tile (after init)
    // phase-B overlay (Ast region only; Bw stays live)
    float* sS    = scr;
    float* sCtx  = scr + 256;
    float* sScore= scr + 512;
    float* sAttn = scr + 576;
    float* sY    = scr + 640;
    float* sRed  = scr + 648;
    float* sH    = scr + 672;

    const int b   = blockIdx.x;
    const int tid = threadIdx.x;
    const int lane = tid & 31, wid = tid >> 5;

    // ---- init: zero h,c for my batch (512 threads cover both halves) ----
    g_HC[b * 512 + tid] = 0.f;

    // ---- precompute P = enc · W1_e^T + b1 : 512 tiles of 64x64x256 ----
    for (int q = 0; q < 4; q++) {
        int tile = b + NBLK * q;           // mt 0..127, nt 0..3
        int mt = tile >> 2, nt = tile & 3;
        gemm64_full(enc + mt * 64 * 256, 256,
                    w1 + nt * 64 * 768 + 512, 768,
                    g_P + mt * 64 * 256 + nt * 64, 256,
                    2, b1 + nt * 64, Ast, Bw);
    }
    grid_barrier();

    // ---- decode my fixed per-step GEMM task ----
    const float* taskA = 0;  const float* taskW = 0;
    float* taskC = 0; int taskLdw = 0, taskLdc = 0;
    if (b < 32) {
        int kc = b >> 3, mt = (b >> 2) & 1, nt = b & 3;
        taskA = g_HC + mt * 64 * 512 + kc * 128;
        taskW = w1 + nt * 64 * 768 + kc * 128;  taskLdw = 768;
        taskC = g_Sp[kc] + mt * 64 * 256 + nt * 64;  taskLdc = 256;
    } else if (b < 96) {
        int g = b - 32;
        int kc = g >> 5, mt = (g >> 4) & 1, nt = g & 15;
        taskA = g_HC + mt * 64 * 512 + kc * 128;
        taskW = whh + nt * 64 * 256 + kc * 128;  taskLdw = 256;
        taskC = g_Gp[kc] + mt * 64 * 1024 + nt * 64;  taskLdc = 1024;
    }

    // ---- stage per-batch data + persistent weight tile in smem (once) ----
    for (int i = tid * 4; i < 16384; i += NTHR * 4) {
        *(float4*)&sEnc[i] = *(const float4*)&enc[b * 16384 + i];
        *(float4*)&sP[i]   = *(const float4*)&g_P[b * 16384 + i];
    }
    if (tid < 256) sW2[tid] = w2[tid];
    if (taskW) stage64x128(taskW, taskLdw, Bw);
    __syncthreads();

    // =======================================================================
    for (int t = 0; t < 64; t++) {
        // ---- phase A: one 64x64x128 task per block (B operand resident) ---
        if (taskA) {
            stage64x128(taskA, 512, Ast);
            __syncthreads();
            unsigned long long acc[2][2];
            acc[0][0] = acc[0][1] = acc[1][0] = acc[1][1] = 0ull;
            mma128(Ast, Bw, acc);
            epilogue(acc, taskC, taskLdc, 0);
        }
        grid_barrier();

        // ---- phase B: per-batch attention + LSTM update -------------------
        // prefetch gate partials early so their L2 latency overlaps scores
        float gp0 = 0.f, gp1 = 0.f, gp2 = 0.f, gp3 = 0.f;
        if (tid < 256) {
            gp0 = g_Gp[0][b * 1024 + 0 * 256 + tid] + g_Gp[1][b * 1024 + 0 * 256 + tid];
            gp1 = g_Gp[0][b * 1024 + 1 * 256 + tid] + g_Gp[1][b * 1024 + 1 * 256 + tid];
            gp2 = g_Gp[0][b * 1024 + 2 * 256 + tid] + g_Gp[1][b * 1024 + 2 * 256 + tid];
            gp3 = g_Gp[0][b * 1024 + 3 * 256 + tid] + g_Gp[1][b * 1024 + 3 * 256 + tid];
            sS[tid] = g_Sp[0][b * 256 + tid] + g_Sp[1][b * 256 + tid]
                    + g_Sp[2][b * 256 + tid] + g_Sp[3][b * 256 + tid];
        }
        __syncthreads();

        // scores: 16 warps x 4 windows, 256-dot with HW tanh
        for (int ww = wid; ww < 64; ww += 16) {
            const float* Pp = &sP[ww * 256];
            float part = 0.f;
#pragma unroll
            for (int j = 0; j < 8; j++) {
                int e = lane + 32 * j;
                part += sW2[e] * tanh_fast(Pp[e] + sS[e]);
            }
#pragma unroll
            for (int o = 16; o; o >>= 1) part += __shfl_xor_sync(0xffffffffu, part, o);
            if (lane == 0) sScore[ww] = part + b2[0];
        }
        __syncthreads();

        // softmax over 64 windows
        if (wid == 0) {
            float v = fmaxf(sScore[lane], sScore[lane + 32]);
#pragma unroll
            for (int o = 16; o; o >>= 1) v = fmaxf(v, __shfl_xor_sync(0xffffffffu, v, o));
            if (lane == 0) sRed[0] = v;
        }
        __syncthreads();
        if (tid < 64) sAttn[tid] = __expf(sScore[tid] - sRed[0]);
        __syncthreads();
        if (wid == 0) {
            float v = sAttn[lane] + sAttn[lane + 32];
#pragma unroll
            for (int o = 16; o; o >>= 1) v += __shfl_xor_sync(0xffffffffu, v, o);
            if (lane == 0) sRed[1] = v;
        }
        __syncthreads();
        float inv = 1.f / sRed[1];

        // context[e] = sum_w attn[w] * enc[b,w,e]  (all smem)
        if (tid < 256) {
            float acc = 0.f;
#pragma unroll 8
            for (int w = 0; w < 64; w++) acc += sAttn[w] * sEnc[w * 256 + tid];
            sCtx[tid] = acc * inv;
        }
        __syncthreads();

        // y_tilde = fc([ctx, y_t]) : 4 warps, K=260
        if (wid < 4) {
            float acc = 0.f;
            const float* fr = &fcw[wid * 260];
            for (int e = lane; e < 256; e += 32) acc += fr[e] * sCtx[e];
#pragma unroll
            for (int o = 16; o; o >>= 1) acc += __shfl_xor_sync(0xffffffffu, acc, o);
            if (lane == 0) {
                float yv = 0.f;
                const float* yp = &yh[(b * 64 + t) * 4];
#pragma unroll
                for (int f = 0; f < 4; f++) yv += fr[256 + f] * yp[f];
                sY[wid] = acc + yv + fcb[wid];
            }
        }
        __syncthreads();

        // gates (prefetched partials + fold y_tilde·w_ih^T) + LSTM cell
        if (tid < 256) {
            int j = tid;
            float g[4];
            float gpv[4] = {gp0, gp1, gp2, gp3};
#pragma unroll
            for (int q = 0; q < 4; q++) {
                int d = q * 256 + j;
                float4 wr = *(const float4*)&wih[d * 4];
                g[q] = gpv[q] + bih[d] + bhh[d]
                     + wr.x * sY[0] + wr.y * sY[1] + wr.z * sY[2] + wr.w * sY[3];
            }
            float ig = 1.f / (1.f + expf(-g[0]));
            float fg = 1.f / (1.f + expf(-g[1]));
            float gg = tanhf(g[2]);
            float og = 1.f / (1.f + expf(-g[3]));
            float c_old = g_HC[b * 512 + 256 + j];
            float c_new = fg * c_old + ig * gg;
            float h_new = og * tanhf(c_new);
            g_HC[b * 512 + j]       = h_new;
            g_HC[b * 512 + 256 + j] = c_new;
            if (t == 63) sH[j] = h_new;
        }

        // final output at last step: out[b,:] = fcf([h, ctx])
        if (t == 63) {
            __syncthreads();
            if (wid < 4) {
                float acc = 0.f;
                const float* fr = &fcfw[wid * 512];
                for (int i = lane; i < 512; i += 32) {
                    float v = (i < 256) ? sH[i] : sCtx[i - 256];
                    acc += fr[i] * v;
                }
#pragma unroll
                for (int o = 16; o; o >>= 1) acc += __shfl_xor_sync(0xffffffffu, acc, o);
                if (lane == 0) out[b * 4 + wid] = acc + fcfb[wid];
            }
        }
        grid_barrier();   // h,c visible to next step's phase A
    }
}

// ---------------------------------------------------------------------------
extern "C" void kernel_launch(void* const* d_in, const int* in_sizes, int n_in,
                              void* d_out, int out_size) {
    const float* enc  = (const float*)d_in[0];
    const float* yh   = (const float*)d_in[1];
    const float* w1   = (const float*)d_in[2];
    const float* b1   = (const float*)d_in[3];
    const float* w2   = (const float*)d_in[4];
    const float* b2   = (const float*)d_in[5];
    const float* wih  = (const float*)d_in[6];
    const float* whh  = (const float*)d_in[7];
    const float* bih  = (const float*)d_in[8];
    const float* bhh  = (const float*)d_in[9];
    const float* fcw  = (const float*)d_in[10];
    const float* fcb  = (const float*)d_in[11];
    const float* fcfw = (const float*)d_in[12];
    const float* fcfb = (const float*)d_in[13];
    float* out = (float*)d_out;

    const int smem_bytes = (16384 + 16384 + 256 + 16384) * 4;   // 193 KB
    static int configured = 0;
    if (!configured) {
        cudaFuncSetAttribute(decoder_persistent,
                             cudaFuncAttributeMaxDynamicSharedMemorySize, smem_bytes);
        configured = 1;
    }
    decoder_persistent<<<NBLK, NTHR, smem_bytes>>>(
        enc, yh, w1, b1, w2, b2, wih, whh, bih, bhh, fcw, fcb, fcfw, fcfb, out);
}

// round 8
// speedup vs baseline: 1.1434x; 1.1434x over previous
#include <cuda_runtime.h>
#include <math.h>

#define Bn 128
#define Wn 64
#define En 256
#define Dn 256

#define NBLK 128
#define NTHR 256

// __device__ scratch (allocation-free rule)
__device__ float g_P[Bn * Wn * En];          // P[b,w,e] (8 MB)
__device__ float g_HC[Bn * 2 * Dn];          // [b][0:256]=h, [b][256:512]=c
__device__ float g_Sp[4][Bn * En];           // S K-partials
__device__ float g_Gp[2][Bn * 4 * Dn];       // Ghh K-partials
__device__ unsigned g_bar_gen;               // monotonic generation (replay-safe)
__device__ unsigned g_bar_cnt;               // arrivals, returns to 0 each barrier

// ---------------------------------------------------------------------------
__device__ __forceinline__ float tanh_fast(float x) {
    float y;
    asm("tanh.approx.f32 %0, %1;" : "=f"(y) : "f"(x));
    return y;
}
__device__ __forceinline__ unsigned long long pack2(float x, float y) {
    unsigned long long r;
    asm("mov.b64 %0, {%1, %2};" : "=l"(r) : "f"(x), "f"(y));
    return r;
}
__device__ __forceinline__ unsigned long long fma2(unsigned long long a,
                                                   unsigned long long b,
                                                   unsigned long long c) {
    unsigned long long d;
    asm("fma.rn.f32x2 %0, %1, %2, %3;" : "=l"(d) : "l"(a), "l"(b), "l"(c));
    return d;
}
__device__ __forceinline__ float2 unpack2(unsigned long long v) {
    float lo, hi;
    asm("mov.b64 {%0, %1}, %2;" : "=f"(lo), "=f"(hi) : "l"(v));
    return make_float2(lo, hi);
}

// Grid barrier: REDG fire-and-forget arrivals + block-0 releaser.
// Arrival serialization ~110 cyc (vs ~3500 for atomicAdd-with-return);
// visibility via release/acquire chain, no MEMBAR.GPU on the critical path.
__device__ __forceinline__ void grid_barrier() {
    __syncthreads();
    if (threadIdx.x == 0) {
        unsigned gen;
        asm volatile("ld.acquire.gpu.global.u32 %0, [%1];"
                     : "=r"(gen) : "l"(&g_bar_gen));
        if (blockIdx.x == 0) {
            unsigned c;
            do {
                asm volatile("ld.acquire.gpu.global.u32 %0, [%1];"
                             : "=r"(c) : "l"(&g_bar_cnt));
            } while (c != NBLK - 1);
            asm volatile("st.relaxed.gpu.global.u32 [%0], %1;"
                         :: "l"(&g_bar_cnt), "r"(0u));
            asm volatile("st.release.gpu.global.u32 [%0], %1;"
                         :: "l"(&g_bar_gen), "r"(gen + 1u));
        } else {
            asm volatile("red.release.gpu.global.add.u32 [%0], %1;"
                         :: "l"(&g_bar_cnt), "r"(1u));
            unsigned g2;
            do {
                asm volatile("ld.acquire.gpu.global.u32 %0, [%1];"
                             : "=r"(g2) : "l"(&g_bar_gen));
            } while (g2 == gen);
        }
    }
    __syncthreads();
}

// ---------------------------------------------------------------------------
// Stage 64 rows x 128 k of X (row-major ldx) into Xst[k][r] (stride 64).
__device__ __forceinline__ void stage64x128(const float* __restrict__ Xp, int ldx,
                                            float* __restrict__ Xst) {
    const int tid = threadIdx.x;
    const int r  = tid & 63;
    const int kg = tid >> 6;
#pragma unroll
    for (int q = 0; q < 8; q++) {
        int k4 = (kg + q * 4) << 2;
        float4 v = *(const float4*)(Xp + r * ldx + k4);
        Xst[(k4 + 0) * 64 + r] = v.x;
        Xst[(k4 + 1) * 64 + r] = v.y;
        Xst[(k4 + 2) * 64 + r] = v.z;
        Xst[(k4 + 3) * 64 + r] = v.w;
    }
}

// 64x64 x 128k accumulate with packed f32x2 FMA. acc[4][2] packed pairs.
__device__ __forceinline__ void mma128(const float* __restrict__ Ast,
                                       const float* __restrict__ Bst,
                                       unsigned long long acc[4][2]) {
    const int ty = threadIdx.x >> 4, tx = threadIdx.x & 15;
#pragma unroll 8
    for (int k = 0; k < 128; k++) {
        float4 a = *(const float4*)&Ast[k * 64 + ty * 4];
        ulonglong2 b = *(const ulonglong2*)&Bst[k * 64 + tx * 4];
        unsigned long long a0 = pack2(a.x, a.x);
        unsigned long long a1 = pack2(a.y, a.y);
        unsigned long long a2 = pack2(a.z, a.z);
        unsigned long long a3 = pack2(a.w, a.w);
        acc[0][0] = fma2(a0, b.x, acc[0][0]); acc[0][1] = fma2(a0, b.y, acc[0][1]);
        acc[1][0] = fma2(a1, b.x, acc[1][0]); acc[1][1] = fma2(a1, b.y, acc[1][1]);
        acc[2][0] = fma2(a2, b.x, acc[2][0]); acc[2][1] = fma2(a2, b.y, acc[2][1]);
        acc[3][0] = fma2(a3, b.x, acc[3][0]); acc[3][1] = fma2(a3, b.y, acc[3][1]);
    }
}

__device__ __forceinline__ void epilogue(unsigned long long acc[4][2],
                                         float* __restrict__ Cptr, int ldc,
                                         const float* __restrict__ bias) {
    const int ty = threadIdx.x >> 4, tx = threadIdx.x & 15;
    float4 bb = make_float4(0.f, 0.f, 0.f, 0.f);
    if (bias) bb = *(const float4*)&bias[tx * 4];
#pragma unroll
    for (int i = 0; i < 4; i++) {
        float2 lo = unpack2(acc[i][0]);
        float2 hi = unpack2(acc[i][1]);
        float4 o;
        o.x = lo.x + bb.x; o.y = lo.y + bb.y;
        o.z = hi.x + bb.z; o.w = hi.y + bb.w;
        *(float4*)&Cptr[(ty * 4 + i) * ldc + tx * 4] = o;
    }
}

// Full tile GEMM (stages both operands) for the precompute.
__device__ __forceinline__ void gemm64_full(
    const float* __restrict__ Aptr, int lda,
    const float* __restrict__ Bptr, int ldb,
    float* __restrict__ Cptr, int ldc,
    int nchunk, const float* __restrict__ bias,
    float* __restrict__ Ast, float* __restrict__ Bst)
{
    unsigned long long acc[4][2];
#pragma unroll
    for (int i = 0; i < 4; i++) { acc[i][0] = 0ull; acc[i][1] = 0ull; }
    for (int c = 0; c < nchunk; c++) {
        stage64x128(Aptr + c * 128, lda, Ast);
        stage64x128(Bptr + c * 128, ldb, Bst);
        __syncthreads();
        mma128(Ast, Bst, acc);
        __syncthreads();
    }
    epilogue(acc, Cptr, ldc, bias);
}

// ---------------------------------------------------------------------------
__global__ __launch_bounds__(NTHR, 1)
void decoder_persistent(
    const float* __restrict__ enc,  const float* __restrict__ yh,
    const float* __restrict__ w1,   const float* __restrict__ b1,
    const float* __restrict__ w2,   const float* __restrict__ b2,
    const float* __restrict__ wih,  const float* __restrict__ whh,
    const float* __restrict__ bih,  const float* __restrict__ bhh,
    const float* __restrict__ fcw,  const float* __restrict__ fcb,
    const float* __restrict__ fcfw, const float* __restrict__ fcfb,
    float* __restrict__ out)
{
    extern __shared__ float sm[];
    float* sEnc = sm;            // 16384
    float* sP   = sm + 16384;    // 16384
    float* sW2  = sm + 32768;    // 256
    float* scr  = sm + 33024;    // 16384: [Ast 8192 | Bw 8192]
    float* Ast  = scr;
    float* Bw   = scr + 8192;    // persistent per-block weight tile (after init)
    // phase-B overlay (Ast region only; Bw stays live)
    float* sS    = scr;
    float* sCtx  = scr + 256;
    float* sScore= scr + 512;
    float* sAttn = scr + 576;
    float* sY    = scr + 640;
    float* sRed  = scr + 648;
    float* sH    = scr + 672;

    const int b   = blockIdx.x;
    const int tid = threadIdx.x;
    const int lane = tid & 31, wid = tid >> 5;

    // ---- init: zero h,c for my batch ----
    g_HC[b * 512 + tid]       = 0.f;
    g_HC[b * 512 + 256 + tid] = 0.f;

    // ---- precompute P = enc · W1_e^T + b1 : 512 tiles of 64x64x256 ----
    for (int q = 0; q < 4; q++) {
        int tile = b + NBLK * q;           // mt 0..127, nt 0..3
        int mt = tile >> 2, nt = tile & 3;
        gemm64_full(enc + mt * 64 * 256, 256,
                    w1 + nt * 64 * 768 + 512, 768,
                    g_P + mt * 64 * 256 + nt * 64, 256,
                    2, b1 + nt * 64, Ast, Bw);
    }
    grid_barrier();

    // ---- decode my fixed per-step GEMM task ----
    const float* taskA = 0;  const float* taskW = 0;
    float* taskC = 0; int taskLdw = 0, taskLdc = 0;
    if (b < 32) {
        int kc = b >> 3, mt = (b >> 2) & 1, nt = b & 3;
        taskA = g_HC + mt * 64 * 512 + kc * 128;
        taskW = w1 + nt * 64 * 768 + kc * 128;  taskLdw = 768;
        taskC = g_Sp[kc] + mt * 64 * 256 + nt * 64;  taskLdc = 256;
    } else if (b < 96) {
        int g = b - 32;
        int kc = g >> 5, mt = (g >> 4) & 1, nt = g & 15;
        taskA = g_HC + mt * 64 * 512 + kc * 128;
        taskW = whh + nt * 64 * 256 + kc * 128;  taskLdw = 256;
        taskC = g_Gp[kc] + mt * 64 * 1024 + nt * 64;  taskLdc = 1024;
    }

    // ---- stage per-batch data + persistent weight tile in smem (once) ----
    for (int i = tid * 4; i < 16384; i += NTHR * 4) {
        *(float4*)&sEnc[i] = *(const float4*)&enc[b * 16384 + i];
        *(float4*)&sP[i]   = *(const float4*)&g_P[b * 16384 + i];
    }
    sW2[tid] = w2[tid];
    if (taskW) stage64x128(taskW, taskLdw, Bw);
    __syncthreads();

    // =======================================================================
    for (int t = 0; t < 64; t++) {
        // ---- phase A: one 64x64x128 task per block (B operand resident) ---
        if (taskA) {
            stage64x128(taskA, 512, Ast);
            __syncthreads();
            unsigned long long acc[4][2];
#pragma unroll
            for (int i = 0; i < 4; i++) { acc[i][0] = 0ull; acc[i][1] = 0ull; }
            mma128(Ast, Bw, acc);
            epilogue(acc, taskC, taskLdc, 0);
        }
        grid_barrier();

        // ---- phase B: per-batch attention + LSTM update -------------------
        // prefetch gate partials early so their L2 latency overlaps scores
        float gp0, gp1, gp2, gp3;
        {
            gp0 = g_Gp[0][b * 1024 + 0 * 256 + tid] + g_Gp[1][b * 1024 + 0 * 256 + tid];
            gp1 = g_Gp[0][b * 1024 + 1 * 256 + tid] + g_Gp[1][b * 1024 + 1 * 256 + tid];
            gp2 = g_Gp[0][b * 1024 + 2 * 256 + tid] + g_Gp[1][b * 1024 + 2 * 256 + tid];
            gp3 = g_Gp[0][b * 1024 + 3 * 256 + tid] + g_Gp[1][b * 1024 + 3 * 256 + tid];
            sS[tid] = g_Sp[0][b * 256 + tid] + g_Sp[1][b * 256 + tid]
                    + g_Sp[2][b * 256 + tid] + g_Sp[3][b * 256 + tid];
        }
        __syncthreads();

        // scores: 8 warps x 8 windows, 256-dot with HW tanh
        for (int ww = wid; ww < 64; ww += 8) {
            const float* Pp = &sP[ww * 256];
            float part = 0.f;
#pragma unroll
            for (int j = 0; j < 8; j++) {
                int e = lane + 32 * j;
                part += sW2[e] * tanh_fast(Pp[e] + sS[e]);
            }
#pragma unroll
            for (int o = 16; o; o >>= 1) part += __shfl_xor_sync(0xffffffffu, part, o);
            if (lane == 0) sScore[ww] = part + b2[0];
        }
        __syncthreads();

        // softmax over 64 windows
        if (wid == 0) {
            float v = fmaxf(sScore[lane], sScore[lane + 32]);
#pragma unroll
            for (int o = 16; o; o >>= 1) v = fmaxf(v, __shfl_xor_sync(0xffffffffu, v, o));
            if (lane == 0) sRed[0] = v;
        }
        __syncthreads();
        if (tid < 64) sAttn[tid] = __expf(sScore[tid] - sRed[0]);
        __syncthreads();
        if (wid == 0) {
            float v = sAttn[lane] + sAttn[lane + 32];
#pragma unroll
            for (int o = 16; o; o >>= 1) v += __shfl_xor_sync(0xffffffffu, v, o);
            if (lane == 0) sRed[1] = v;
        }
        __syncthreads();
        float inv = 1.f / sRed[1];

        // context[e] = sum_w attn[w] * enc[b,w,e]  (all smem)
        {
            float acc = 0.f;
#pragma unroll 8
            for (int w = 0; w < 64; w++) acc += sAttn[w] * sEnc[w * 256 + tid];
            sCtx[tid] = acc * inv;
        }
        __syncthreads();

        // y_tilde = fc([ctx, y_t]) : 4 warps, K=260
        if (wid < 4) {
            float acc = 0.f;
            const float* fr = &fcw[wid * 260];
            for (int e = lane; e < 256; e += 32) acc += fr[e] * sCtx[e];
#pragma unroll
            for (int o = 16; o; o >>= 1) acc += __shfl_xor_sync(0xffffffffu, acc, o);
            if (lane == 0) {
                float yv = 0.f;
                const float* yp = &yh[(b * 64 + t) * 4];
#pragma unroll
                for (int f = 0; f < 4; f++) yv += fr[256 + f] * yp[f];
                sY[wid] = acc + yv + fcb[wid];
            }
        }
        __syncthreads();

        // gates (prefetched partials + fold y_tilde·w_ih^T) + LSTM cell
        {
            int j = tid;
            float g[4];
            float gpv[4] = {gp0, gp1, gp2, gp3};
#pragma unroll
            for (int q = 0; q < 4; q++) {
                int d = q * 256 + j;
                float4 wr = *(const float4*)&wih[d * 4];
                g[q] = gpv[q] + bih[d] + bhh[d]
                     + wr.x * sY[0] + wr.y * sY[1] + wr.z * sY[2] + wr.w * sY[3];
            }
            float ig = 1.f / (1.f + expf(-g[0]));
            float fg = 1.f / (1.f + expf(-g[1]));
            float gg = tanhf(g[2]);
            float og = 1.f / (1.f + expf(-g[3]));
            float c_old = g_HC[b * 512 + 256 + j];
            float c_new = fg * c_old + ig * gg;
            float h_new = og * tanhf(c_new);
            g_HC[b * 512 + j]       = h_new;
            g_HC[b * 512 + 256 + j] = c_new;
            if (t == 63) sH[j] = h_new;
        }

        // final output at last step: out[b,:] = fcf([h, ctx])
        if (t == 63) {
            __syncthreads();
            if (wid < 4) {
                float acc = 0.f;
                const float* fr = &fcfw[wid * 512];
                for (int i = lane; i < 512; i += 32) {
                    float v = (i < 256) ? sH[i] : sCtx[i - 256];
                    acc += fr[i] * v;
                }
#pragma unroll
                for (int o = 16; o; o >>= 1) acc += __shfl_xor_sync(0xffffffffu, acc, o);
                if (lane == 0) out[b * 4 + wid] = acc + fcfb[wid];
            }
        }
        grid_barrier();   // h,c visible to next step's phase A
    }
}

// ---------------------------------------------------------------------------
extern "C" void kernel_launch(void* const* d_in, const int* in_sizes, int n_in,
                              void* d_out, int out_size) {
    const float* enc  = (const float*)d_in[0];
    const float* yh   = (const float*)d_in[1];
    const float* w1   = (const float*)d_in[2];
    const float* b1   = (const float*)d_in[3];
    const float* w2   = (const float*)d_in[4];
    const float* b2   = (const float*)d_in[5];
    const float* wih  = (const float*)d_in[6];
    const float* whh  = (const float*)d_in[7];
    const float* bih  = (const float*)d_in[8];
    const float* bhh  = (const float*)d_in[9];
    const float* fcw  = (const float*)d_in[10];
    const float* fcb  = (const float*)d_in[11];
    const float* fcfw = (const float*)d_in[12];
    const float* fcfb = (const float*)d_in[13];
    float* out = (float*)d_out;

    const int smem_bytes = (16384 + 16384 + 256 + 16384) * 4;   // 193 KB
    static int configured = 0;
    if (!configured) {
        cudaFuncSetAttribute(decoder_persistent,
                             cudaFuncAttributeMaxDynamicSharedMemorySize, smem_bytes);
        configured = 1;
    }
    decoder_persistent<<<NBLK, NTHR, smem_bytes>>>(
        enc, yh, w1, b1, w2, b2, wih, whh, bih, bhh, fcw, fcb, fcfw, fcfb, out);
}

// round 11
// speedup vs baseline: 1.2302x; 1.0759x over previous
#include <cuda_runtime.h>
#include <stdint.h>
#include <math.h>

#define Bn 128
#define Wn 64
#define En 256
#define Dn 256

#define NBLK 128
#define NTHR 256

// __device__ scratch (allocation-free rule)
__device__ float g_P[Bn * Wn * En];          // P[b,w,e] (8 MB)
__device__ float g_HC[Bn * 2 * Dn];          // [b][0:256]=h, [b][256:512]=c
__device__ float g_Sp[8][Bn * En];           // S kc-partials (K=64 each)
__device__ float g_Gp[2][Bn * 4 * Dn];       // Ghh kc-partials (K=128 each)
__device__ unsigned g_bar_gen;               // main barrier generation
__device__ unsigned g_bar_cnt;               // main barrier arrivals (self-reset)
__device__ unsigned g_cntS;                  // monotonic S-done counter
__device__ unsigned g_cntG;                  // monotonic G-done counter

// ---------------------------------------------------------------------------
__device__ __forceinline__ float tanh_fast(float x) {
    float y;
    asm("tanh.approx.f32 %0, %1;" : "=f"(y) : "f"(x));
    return y;
}
__device__ __forceinline__ unsigned long long pack2(float x, float y) {
    unsigned long long r;
    asm("mov.b64 %0, {%1, %2};" : "=l"(r) : "f"(x), "f"(y));
    return r;
}
__device__ __forceinline__ unsigned long long fma2(unsigned long long a,
                                                   unsigned long long b,
                                                   unsigned long long c) {
    unsigned long long d;
    asm("fma.rn.f32x2 %0, %1, %2, %3;" : "=l"(d) : "l"(a), "l"(b), "l"(c));
    return d;
}
__device__ __forceinline__ float2 unpack2(unsigned long long v) {
    float lo, hi;
    asm("mov.b64 {%0, %1}, %2;" : "=f"(lo), "=f"(hi) : "l"(v));
    return make_float2(lo, hi);
}

// Main grid barrier (R8-proven): REDG arrivals + block-0 releaser.
__device__ __forceinline__ void grid_barrier() {
    __syncthreads();
    if (threadIdx.x == 0) {
        unsigned gen;
        asm volatile("ld.acquire.gpu.global.u32 %0, [%1];"
                     : "=r"(gen) : "l"(&g_bar_gen));
        if (blockIdx.x == 0) {
            unsigned c;
            do {
                asm volatile("ld.acquire.gpu.global.u32 %0, [%1];"
                             : "=r"(c) : "l"(&g_bar_cnt));
            } while (c != NBLK - 1);
            asm volatile("st.relaxed.gpu.global.u32 [%0], %1;"
                         :: "l"(&g_bar_cnt), "r"(0u));
            asm volatile("st.release.gpu.global.u32 [%0], %1;"
                         :: "l"(&g_bar_gen), "r"(gen + 1u));
        } else {
            asm volatile("red.release.gpu.global.add.u32 [%0], %1;"
                         :: "l"(&g_bar_cnt), "r"(1u));
            unsigned g2;
            do {
                asm volatile("ld.acquire.gpu.global.u32 %0, [%1];"
                             : "=r"(g2) : "l"(&g_bar_gen));
            } while (g2 == gen);
        }
    }
    __syncthreads();
}

// Monotonic flag: arrive (tid0 after __syncthreads) / wait until >= target.
__device__ __forceinline__ void flag_arrive(unsigned* p) {
    asm volatile("red.release.gpu.global.add.u32 [%0], %1;"
                 :: "l"(p), "r"(1u));
}
__device__ __forceinline__ void flag_wait_ge(unsigned* p, unsigned target) {
    if (threadIdx.x == 0) {
        unsigned v;
        do {
            asm volatile("ld.acquire.gpu.global.u32 %0, [%1];"
                         : "=r"(v) : "l"(p));
        } while (v < target);
    }
    __syncthreads();
}

// ---------------------------------------------------------------------------
// Stage 64 rows x K cols of X (row-major ldx) into Xst[k][r] (stride 64).
__device__ __forceinline__ void stageK(const float* __restrict__ Xp, int ldx,
                                       float* __restrict__ Xst, int K) {
    const int tid = threadIdx.x;
    const int r  = tid & 63;
    const int kg = tid >> 6;
    const int nq = K >> 4;
#pragma unroll
    for (int q = 0; q < nq; q++) {
        int k4 = (kg + q * 4) << 2;
        float4 v = *(const float4*)(Xp + r * ldx + k4);
        Xst[(k4 + 0) * 64 + r] = v.x;
        Xst[(k4 + 1) * 64 + r] = v.y;
        Xst[(k4 + 2) * 64 + r] = v.z;
        Xst[(k4 + 3) * 64 + r] = v.w;
    }
}

// 64x64 x K accumulate with packed f32x2 FMA. acc[4][2] packed pairs.
__device__ __forceinline__ void mmaK(const float* __restrict__ Ast,
                                     const float* __restrict__ Bst,
                                     unsigned long long acc[4][2], int K) {
    const int ty = threadIdx.x >> 4, tx = threadIdx.x & 15;
#pragma unroll 8
    for (int k = 0; k < K; k++) {
        float4 a = *(const float4*)&Ast[k * 64 + ty * 4];
        ulonglong2 b = *(const ulonglong2*)&Bst[k * 64 + tx * 4];
        unsigned long long a0 = pack2(a.x, a.x);
        unsigned long long a1 = pack2(a.y, a.y);
        unsigned long long a2 = pack2(a.z, a.z);
        unsigned long long a3 = pack2(a.w, a.w);
        acc[0][0] = fma2(a0, b.x, acc[0][0]); acc[0][1] = fma2(a0, b.y, acc[0][1]);
        acc[1][0] = fma2(a1, b.x, acc[1][0]); acc[1][1] = fma2(a1, b.y, acc[1][1]);
        acc[2][0] = fma2(a2, b.x, acc[2][0]); acc[2][1] = fma2(a2, b.y, acc[2][1]);
        acc[3][0] = fma2(a3, b.x, acc[3][0]); acc[3][1] = fma2(a3, b.y, acc[3][1]);
    }
}

__device__ __forceinline__ void epilogue(unsigned long long acc[4][2],
                                         float* __restrict__ Cptr, int ldc,
                                         const float* __restrict__ bias) {
    const int ty = threadIdx.x >> 4, tx = threadIdx.x & 15;
    float4 bb = make_float4(0.f, 0.f, 0.f, 0.f);
    if (bias) bb = *(const float4*)&bias[tx * 4];
#pragma unroll
    for (int i = 0; i < 4; i++) {
        float2 lo = unpack2(acc[i][0]);
        float2 hi = unpack2(acc[i][1]);
        float4 o;
        o.x = lo.x + bb.x; o.y = lo.y + bb.y;
        o.z = hi.x + bb.z; o.w = hi.y + bb.w;
        *(float4*)&Cptr[(ty * 4 + i) * ldc + tx * 4] = o;
    }
}

// Full tile GEMM (stages both operands) for the one-time P precompute.
__device__ __forceinline__ void gemm64_full(
    const float* __restrict__ Aptr, int lda,
    const float* __restrict__ Bptr, int ldb,
    float* __restrict__ Cptr, int ldc,
    int nchunk, const float* __restrict__ bias,
    float* __restrict__ Ast, float* __restrict__ Bst)
{
    unsigned long long acc[4][2];
#pragma unroll
    for (int i = 0; i < 4; i++) { acc[i][0] = 0ull; acc[i][1] = 0ull; }
    for (int c = 0; c < nchunk; c++) {
        stageK(Aptr + c * 128, lda, Ast, 128);
        stageK(Bptr + c * 128, ldb, Bst, 128);
        __syncthreads();
        mmaK(Ast, Bst, acc, 128);
        __syncthreads();
    }
    epilogue(acc, Cptr, ldc, bias);
}

// ---------------------------------------------------------------------------
__global__ __launch_bounds__(NTHR, 1)
void decoder_persistent(
    const float* __restrict__ enc,  const float* __restrict__ yh,
    const float* __restrict__ w1,   const float* __restrict__ b1,
    const float* __restrict__ w2,   const float* __restrict__ b2,
    const float* __restrict__ wih,  const float* __restrict__ whh,
    const float* __restrict__ bih,  const float* __restrict__ bhh,
    const float* __restrict__ fcw,  const float* __restrict__ fcb,
    const float* __restrict__ fcfw, const float* __restrict__ fcfb,
    float* __restrict__ out)
{
    extern __shared__ float sm[];
    float* sEnc = sm;            // 16384
    float* sP   = sm + 16384;    // 16384
    float* sW2  = sm + 32768;    // 256
    float* scr  = sm + 33024;    // 16384: [Ast 8192 | Bw 8192]
    float* Ast  = scr;
    float* Bw   = scr + 8192;    // persistent per-block weight tile (after init)
    // phase-B overlay (Ast region only; Bw stays live)
    float* sS    = scr;
    float* sCtx  = scr + 256;
    float* sScore= scr + 512;
    float* sAttn = scr + 576;
    float* sY    = scr + 640;
    float* sRed  = scr + 656;
    float* sH    = scr + 672;

    const int b   = blockIdx.x;
    const int tid = threadIdx.x;
    const int lane = tid & 31, wid = tid >> 5;

    // ---- init: zero h,c for my batch ----
    g_HC[b * 512 + tid]       = 0.f;
    g_HC[b * 512 + 256 + tid] = 0.f;

    // ---- precompute P = enc · W1_e^T + b1 : 512 tiles of 64x64x256 ----
    for (int q = 0; q < 4; q++) {
        int tile = b + NBLK * q;           // mt 0..127, nt 0..3
        int mt = tile >> 2, nt = tile & 3;
        gemm64_full(enc + mt * 64 * 256, 256,
                    w1 + nt * 64 * 768 + 512, 768,
                    g_P + mt * 64 * 256 + nt * 64, 256,
                    2, b1 + nt * 64, Ast, Bw);
    }
    grid_barrier();

    // ---- decode my fixed per-step GEMM task ----
    // blocks 0..63 : S task,  kc=b&7 (K=64), nt=(b>>3)&3, mt=b>>5
    // blocks 64..127: G task, g=b-64: kc=g>>5 (K=128), mt=(g>>4)&1, nt=g&15
    const float* taskA; const float* taskW;
    float* taskC; int taskLdw, taskLdc, taskK;
    unsigned* taskFlag;
    if (b < 64) {
        int kc = b & 7, nt = (b >> 3) & 3, mt = b >> 5;
        taskA = g_HC + mt * 64 * 512 + kc * 64;
        taskW = w1 + nt * 64 * 768 + kc * 64;  taskLdw = 768;
        taskC = g_Sp[kc] + mt * 64 * 256 + nt * 64;  taskLdc = 256;
        taskK = 64;  taskFlag = &g_cntS;
    } else {
        int g = b - 64;
        int kc = g >> 5, mt = (g >> 4) & 1, nt = g & 15;
        taskA = g_HC + mt * 64 * 512 + kc * 128;
        taskW = whh + nt * 64 * 256 + kc * 128;  taskLdw = 256;
        taskC = g_Gp[kc] + mt * 64 * 1024 + nt * 64;  taskLdc = 1024;
        taskK = 128;  taskFlag = &g_cntG;
    }

    // ---- stage per-batch data + persistent weight tile in smem (once) ----
    for (int i = tid * 4; i < 16384; i += NTHR * 4) {
        *(float4*)&sEnc[i] = *(const float4*)&enc[b * 16384 + i];
        *(float4*)&sP[i]   = *(const float4*)&g_P[b * 16384 + i];
    }
    sW2[tid] = w2[tid];
    stageK(taskW, taskLdw, Bw, taskK);
    __syncthreads();

    // =======================================================================
    for (int t = 0; t < 64; t++) {
        const unsigned target = (unsigned)(64 * (t + 1));

        // ---- phase A: one GEMM task per block; arrivals split S vs G ------
        {
            stageK(taskA, 512, Ast, taskK);
            __syncthreads();
            unsigned long long acc[4][2];
#pragma unroll
            for (int i = 0; i < 4; i++) { acc[i][0] = 0ull; acc[i][1] = 0ull; }
            mmaK(Ast, Bw, acc, taskK);
            epilogue(acc, taskC, taskLdc, 0);
            __syncthreads();
            if (tid == 0) flag_arrive(taskFlag);
        }

        // ---- phase B1: attention (needs S only; overlaps G-GEMM) ----------
        flag_wait_ge(&g_cntS, target);
        sS[tid] = g_Sp[0][b * 256 + tid] + g_Sp[1][b * 256 + tid]
                + g_Sp[2][b * 256 + tid] + g_Sp[3][b * 256 + tid]
                + g_Sp[4][b * 256 + tid] + g_Sp[5][b * 256 + tid]
                + g_Sp[6][b * 256 + tid] + g_Sp[7][b * 256 + tid];
        __syncthreads();

        // scores: 8 warps x 8 windows, 256-dot with HW tanh
        for (int ww = wid; ww < 64; ww += 8) {
            const float* Pp = &sP[ww * 256];
            float part = 0.f;
#pragma unroll
            for (int j = 0; j < 8; j++) {
                int e = lane + 32 * j;
                part += sW2[e] * tanh_fast(Pp[e] + sS[e]);
            }
#pragma unroll
            for (int o = 16; o; o >>= 1) part += __shfl_xor_sync(0xffffffffu, part, o);
            if (lane == 0) sScore[ww] = part + b2[0];
        }
        __syncthreads();

        // softmax over 64 windows
        if (wid == 0) {
            float v = fmaxf(sScore[lane], sScore[lane + 32]);
#pragma unroll
            for (int o = 16; o; o >>= 1) v = fmaxf(v, __shfl_xor_sync(0xffffffffu, v, o));
            if (lane == 0) sRed[0] = v;
        }
        __syncthreads();
        if (tid < 64) sAttn[tid] = __expf(sScore[tid] - sRed[0]);
        __syncthreads();
        if (wid == 0) {
            float v = sAttn[lane] + sAttn[lane + 32];
#pragma unroll
            for (int o = 16; o; o >>= 1) v += __shfl_xor_sync(0xffffffffu, v, o);
            if (lane == 0) sRed[1] = v;
        }
        __syncthreads();
        float inv = 1.f / sRed[1];

        // context[e] = sum_w attn[w] * enc[b,w,e]  (all smem)
        {
            float acc = 0.f;
#pragma unroll 8
            for (int w = 0; w < 64; w++) acc += sAttn[w] * sEnc[w * 256 + tid];
            sCtx[tid] = acc * inv;
        }
        __syncthreads();

        // y_tilde = fc([ctx, y_t]) : 4 warps, K=260
        if (wid < 4) {
            float acc = 0.f;
            const float* fr = &fcw[wid * 260];
            for (int e = lane; e < 256; e += 32) acc += fr[e] * sCtx[e];
#pragma unroll
            for (int o = 16; o; o >>= 1) acc += __shfl_xor_sync(0xffffffffu, acc, o);
            if (lane == 0) {
                float yv = 0.f;
                const float* yp = &yh[(b * 64 + t) * 4];
#pragma unroll
                for (int f = 0; f < 4; f++) yv += fr[256 + f] * yp[f];
                sY[wid] = acc + yv + fcb[wid];
            }
        }
        __syncthreads();

        // ---- phase B2: gates + LSTM cell (needs G; usually already done) --
        flag_wait_ge(&g_cntG, target);
        {
            int j = tid;
            float g[4];
#pragma unroll
            for (int q = 0; q < 4; q++) {
                int d = q * 256 + j;
                float4 wr = *(const float4*)&wih[d * 4];
                g[q] = g_Gp[0][b * 1024 + d] + g_Gp[1][b * 1024 + d]
                     + bih[d] + bhh[d]
                     + wr.x * sY[0] + wr.y * sY[1] + wr.z * sY[2] + wr.w * sY[3];
            }
            float ig = 1.f / (1.f + expf(-g[0]));
            float fg = 1.f / (1.f + expf(-g[1]));
            float gg = tanhf(g[2]);
            float og = 1.f / (1.f + expf(-g[3]));
            float c_old = g_HC[b * 512 + 256 + j];
            float c_new = fg * c_old + ig * gg;
            float h_new = og * tanhf(c_new);
            g_HC[b * 512 + j]       = h_new;
            g_HC[b * 512 + 256 + j] = c_new;
            if (t == 63) sH[j] = h_new;
        }

        // final output at last step: out[b,:] = fcf([h, ctx])
        if (t == 63) {
            __syncthreads();
            if (wid < 4) {
                float acc = 0.f;
                const float* fr = &fcfw[wid * 512];
                for (int i = lane; i < 512; i += 32) {
                    float v = (i < 256) ? sH[i] : sCtx[i - 256];
                    acc += fr[i] * v;
                }
#pragma unroll
                for (int o = 16; o; o >>= 1) acc += __shfl_xor_sync(0xffffffffu, acc, o);
                if (lane == 0) out[b * 4 + wid] = acc + fcfb[wid];
            }
        }
        grid_barrier();   // h,c visible to next step's phase A
    }

    // reset monotonic flags for the next graph replay (all arrivals are
    // ordered before the final grid_barrier's observed arrivals)
    if (b == 0 && tid == 0) {
        asm volatile("st.relaxed.gpu.global.u32 [%0], %1;" :: "l"(&g_cntS), "r"(0u));
        asm volatile("st.relaxed.gpu.global.u32 [%0], %1;" :: "l"(&g_cntG), "r"(0u));
    }
}

// ---------------------------------------------------------------------------
extern "C" void kernel_launch(void* const* d_in, const int* in_sizes, int n_in,
                              void* d_out, int out_size) {
    const float* enc  = (const float*)d_in[0];
    const float* yh   = (const float*)d_in[1];
    const float* w1   = (const float*)d_in[2];
    const float* b1   = (const float*)d_in[3];
    const float* w2   = (const float*)d_in[4];
    const float* b2   = (const float*)d_in[5];
    const float* wih  = (const float*)d_in[6];
    const float* whh  = (const float*)d_in[7];
    const float* bih  = (const float*)d_in[8];
    const float* bhh  = (const float*)d_in[9];
    const float* fcw  = (const float*)d_in[10];
    const float* fcb  = (const float*)d_in[11];
    const float* fcfw = (const float*)d_in[12];
    const float* fcfb = (const float*)d_in[13];
    float* out = (float*)d_out;

    const int smem_bytes = (16384 + 16384 + 256 + 16384) * 4;   // ~193 KB
    static int configured = 0;
    if (!configured) {
        cudaFuncSetAttribute(decoder_persistent,
                             cudaFuncAttributeMaxDynamicSharedMemorySize, smem_bytes);
        configured = 1;
    }
    decoder_persistent<<<NBLK, NTHR, smem_bytes>>>(
        enc, yh, w1, b1, w2, b2, wih, whh, bih, bhh, fcw, fcb, fcfw, fcfb, out);
}

// round 12
// speedup vs baseline: 1.3878x; 1.1281x over previous
#include <cuda_runtime.h>
#include <stdint.h>
#include <math.h>

#define NBLK 128
#define NTHR 256

// __device__ scratch (allocation-free rule)
__device__ float g_P[128 * 64 * 256];        // P[b,w,e] (8 MB)
__device__ float g_HC[128 * 512];            // [b][0:256]=h, [b][256:512]=c
__device__ float g_Sp[8][128 * 256];         // S kc-partials (K=64 each)
__device__ float g_Gp[2][128 * 1024];        // Ghh kc-partials (K=128 each)
__device__ unsigned g_cntP, g_cntS, g_cntG, g_cntH;   // monotonic flags
__device__ unsigned g_bar_gen, g_bar_cnt;             // final barrier only

// ---- smem float offsets (total 55840 floats = 223360 B) ----
#define F_ENC   0        // 16384
#define F_P     16384    // 16384
#define F_W2    32768    // 256
#define F_WIH   33024    // 4096
#define F_BIAS  37120    // 1024 (bih+bhh)
#define F_FCW   38144    // 1048 (fcw 1040, pad)
#define F_YH    39192    // 256  (yh[b] all steps)
#define F_CONST 39448    // 8    ([0]=b2, [4..7]=fcb)
#define F_SCR   39456    // 16384 (Ast | Bw; overlay in Ast region)
#define SMEM_BYTES (55840 * 4)

// ---------------------------------------------------------------------------
__device__ __forceinline__ float tanh_fast(float x) {
    float y;
    asm("tanh.approx.f32 %0, %1;" : "=f"(y) : "f"(x));
    return y;
}
__device__ __forceinline__ unsigned long long pack2(float x, float y) {
    unsigned long long r;
    asm("mov.b64 %0, {%1, %2};" : "=l"(r) : "f"(x), "f"(y));
    return r;
}
__device__ __forceinline__ unsigned long long fma2(unsigned long long a,
                                                   unsigned long long b,
                                                   unsigned long long c) {
    unsigned long long d;
    asm("fma.rn.f32x2 %0, %1, %2, %3;" : "=l"(d) : "l"(a), "l"(b), "l"(c));
    return d;
}
__device__ __forceinline__ float2 unpack2(unsigned long long v) {
    float lo, hi;
    asm("mov.b64 {%0, %1}, %2;" : "=f"(lo), "=f"(hi) : "l"(v));
    return make_float2(lo, hi);
}

// fire-and-forget arrival (tid0, after __syncthreads)
__device__ __forceinline__ void flag_arrive(unsigned* p) {
    asm volatile("red.release.gpu.global.add.u32 [%0], %1;" :: "l"(p), "r"(1u));
}
// raw poll (no syncthreads) — caller supplies the block-wide sync
__device__ __forceinline__ void flag_poll_ge(unsigned* p, unsigned target) {
    unsigned v;
    do {
        asm volatile("ld.acquire.gpu.global.u32 %0, [%1];" : "=r"(v) : "l"(p));
    } while (v < target);
}
// block-wide wait: tid0 polls, then syncthreads propagates
__device__ __forceinline__ void flag_wait_ge(unsigned* p, unsigned target) {
    if (threadIdx.x == 0) flag_poll_ge(p, target);
    __syncthreads();
}

// two-hop barrier, used ONCE after the loop (reset safety)
__device__ __forceinline__ void grid_barrier() {
    __syncthreads();
    if (threadIdx.x == 0) {
        unsigned gen;
        asm volatile("ld.acquire.gpu.global.u32 %0, [%1];" : "=r"(gen) : "l"(&g_bar_gen));
        if (blockIdx.x == 0) {
            unsigned c;
            do {
                asm volatile("ld.acquire.gpu.global.u32 %0, [%1];" : "=r"(c) : "l"(&g_bar_cnt));
            } while (c != NBLK - 1);
            asm volatile("st.relaxed.gpu.global.u32 [%0], %1;" :: "l"(&g_bar_cnt), "r"(0u));
            asm volatile("st.release.gpu.global.u32 [%0], %1;" :: "l"(&g_bar_gen), "r"(gen + 1u));
        } else {
            asm volatile("red.release.gpu.global.add.u32 [%0], %1;" :: "l"(&g_bar_cnt), "r"(1u));
            unsigned g2;
            do {
                asm volatile("ld.acquire.gpu.global.u32 %0, [%1];" : "=r"(g2) : "l"(&g_bar_gen));
            } while (g2 == gen);
        }
    }
    __syncthreads();
}

// ---------------------------------------------------------------------------
// Stage 64 rows x K cols of X (row-major ldx) into Xst[k][r] (stride 64).
__device__ __forceinline__ void stageK(const float* __restrict__ Xp, int ldx,
                                       float* __restrict__ Xst, int K) {
    const int tid = threadIdx.x;
    const int r  = tid & 63;
    const int kg = tid >> 6;
    const int nq = K >> 4;
#pragma unroll
    for (int q = 0; q < nq; q++) {
        int k4 = (kg + q * 4) << 2;
        float4 v = *(const float4*)(Xp + r * ldx + k4);
        Xst[(k4 + 0) * 64 + r] = v.x;
        Xst[(k4 + 1) * 64 + r] = v.y;
        Xst[(k4 + 2) * 64 + r] = v.z;
        Xst[(k4 + 3) * 64 + r] = v.w;
    }
}

// 64x64 x K accumulate with packed f32x2 FMA. acc[4][2] packed pairs.
__device__ __forceinline__ void mmaK(const float* __restrict__ Ast,
                                     const float* __restrict__ Bst,
                                     unsigned long long acc[4][2], int K) {
    const int ty = threadIdx.x >> 4, tx = threadIdx.x & 15;
#pragma unroll 8
    for (int k = 0; k < K; k++) {
        float4 a = *(const float4*)&Ast[k * 64 + ty * 4];
        ulonglong2 b = *(const ulonglong2*)&Bst[k * 64 + tx * 4];
        unsigned long long a0 = pack2(a.x, a.x);
        unsigned long long a1 = pack2(a.y, a.y);
        unsigned long long a2 = pack2(a.z, a.z);
        unsigned long long a3 = pack2(a.w, a.w);
        acc[0][0] = fma2(a0, b.x, acc[0][0]); acc[0][1] = fma2(a0, b.y, acc[0][1]);
        acc[1][0] = fma2(a1, b.x, acc[1][0]); acc[1][1] = fma2(a1, b.y, acc[1][1]);
        acc[2][0] = fma2(a2, b.x, acc[2][0]); acc[2][1] = fma2(a2, b.y, acc[2][1]);
        acc[3][0] = fma2(a3, b.x, acc[3][0]); acc[3][1] = fma2(a3, b.y, acc[3][1]);
    }
}

__device__ __forceinline__ void epilogue(unsigned long long acc[4][2],
                                         float* __restrict__ Cptr, int ldc,
                                         const float* __restrict__ bias) {
    const int ty = threadIdx.x >> 4, tx = threadIdx.x & 15;
    float4 bb = make_float4(0.f, 0.f, 0.f, 0.f);
    if (bias) bb = *(const float4*)&bias[tx * 4];
#pragma unroll
    for (int i = 0; i < 4; i++) {
        float2 lo = unpack2(acc[i][0]);
        float2 hi = unpack2(acc[i][1]);
        float4 o;
        o.x = lo.x + bb.x; o.y = lo.y + bb.y;
        o.z = hi.x + bb.z; o.w = hi.y + bb.w;
        *(float4*)&Cptr[(ty * 4 + i) * ldc + tx * 4] = o;
    }
}

// Full tile GEMM (stages both operands) for the one-time P precompute.
__device__ __forceinline__ void gemm64_full(
    const float* __restrict__ Aptr, int lda,
    const float* __restrict__ Bptr, int ldb,
    float* __restrict__ Cptr, int ldc,
    int nchunk, const float* __restrict__ bias,
    float* __restrict__ Ast, float* __restrict__ Bst)
{
    unsigned long long acc[4][2];
#pragma unroll
    for (int i = 0; i < 4; i++) { acc[i][0] = 0ull; acc[i][1] = 0ull; }
    for (int c = 0; c < nchunk; c++) {
        stageK(Aptr + c * 128, lda, Ast, 128);
        stageK(Bptr + c * 128, ldb, Bst, 128);
        __syncthreads();
        mmaK(Ast, Bst, acc, 128);
        __syncthreads();
    }
    epilogue(acc, Cptr, ldc, bias);
}

// ---------------------------------------------------------------------------
__global__ __launch_bounds__(NTHR, 1)
void decoder_persistent(
    const float* __restrict__ enc,  const float* __restrict__ yh,
    const float* __restrict__ w1,   const float* __restrict__ b1,
    const float* __restrict__ w2,   const float* __restrict__ b2,
    const float* __restrict__ wih,  const float* __restrict__ whh,
    const float* __restrict__ bih,  const float* __restrict__ bhh,
    const float* __restrict__ fcw,  const float* __restrict__ fcb,
    const float* __restrict__ fcfw, const float* __restrict__ fcfb,
    float* __restrict__ out)
{
    extern __shared__ float sm[];
    float* sEnc  = sm + F_ENC;
    float* sP    = sm + F_P;
    float* sW2   = sm + F_W2;
    float* sWih  = sm + F_WIH;
    float* sBias = sm + F_BIAS;
    float* sFcw  = sm + F_FCW;
    float* sYh   = sm + F_YH;
    float* sCst  = sm + F_CONST;
    float* scr   = sm + F_SCR;
    float* Ast   = scr;           // up to 8192 floats (K<=128)
    float* Bw    = scr + 8192;    // persistent weight tile
    // phase-B overlay (inside Ast region; Bw untouched)
    float* sS    = scr;
    float* sCtx  = scr + 256;
    float* sScore= scr + 512;     // (unused slots kept for layout clarity)
    float* sAttn = scr + 576;
    float* sWsum = scr + 640;
    float* sY    = scr + 656;
    float* sH    = scr + 672;
    (void)sScore;

    const int b   = blockIdx.x;
    const int tid = threadIdx.x;
    const int lane = tid & 31, wid = tid >> 5;

    // ---- init: zero h,c for my batch ----
    g_HC[b * 512 + tid]       = 0.f;
    g_HC[b * 512 + 256 + tid] = 0.f;

    // ---- precompute P = enc · W1_e^T + b1 : 512 tiles of 64x64x256 ----
    for (int q = 0; q < 4; q++) {
        int tile = b + NBLK * q;           // mt 0..127, nt 0..3
        int mt = tile >> 2, nt = tile & 3;
        gemm64_full(enc + mt * 64 * 256, 256,
                    w1 + nt * 64 * 768 + 512, 768,
                    g_P + mt * 64 * 256 + nt * 64, 256,
                    2, b1 + nt * 64, Ast, Bw);
    }
    __syncthreads();
    if (tid == 0) flag_arrive(&g_cntP);
    flag_wait_ge(&g_cntP, NBLK);

    // ---- decode my fixed per-step GEMM task ----
    // blocks 0..63 : S task,  kc=b&7 (K=64), nt=(b>>3)&3, mt=b>>5
    // blocks 64..127: G task, g=b-64: kc=g>>5 (K=128), mt=(g>>4)&1, nt=g&15
    const float* taskA; const float* taskW;
    float* taskC; int taskLdw, taskLdc, taskK;
    unsigned* taskFlag;
    if (b < 64) {
        int kc = b & 7, nt = (b >> 3) & 3, mt = b >> 5;
        taskA = g_HC + mt * 64 * 512 + kc * 64;
        taskW = w1 + nt * 64 * 768 + kc * 64;  taskLdw = 768;
        taskC = g_Sp[kc] + mt * 64 * 256 + nt * 64;  taskLdc = 256;
        taskK = 64;  taskFlag = &g_cntS;
    } else {
        int g = b - 64;
        int kc = g >> 5, mt = (g >> 4) & 1, nt = g & 15;
        taskA = g_HC + mt * 64 * 512 + kc * 128;
        taskW = whh + nt * 64 * 256 + kc * 128;  taskLdw = 256;
        taskC = g_Gp[kc] + mt * 64 * 1024 + nt * 64;  taskLdc = 1024;
        taskK = 128;  taskFlag = &g_cntG;
    }

    // ---- one-time staging: per-batch data + invariant weights ----
    for (int i = tid * 4; i < 16384; i += NTHR * 4) {
        *(float4*)&sEnc[i] = *(const float4*)&enc[b * 16384 + i];
        *(float4*)&sP[i]   = *(const float4*)&g_P[b * 16384 + i];
    }
    sW2[tid] = w2[tid];
    for (int i = tid * 4; i < 4096; i += NTHR * 4)
        *(float4*)&sWih[i] = *(const float4*)&wih[i];
    {
        int i = tid * 4;
        float4 v1 = *(const float4*)&bih[i];
        float4 v2 = *(const float4*)&bhh[i];
        float4 o; o.x = v1.x + v2.x; o.y = v1.y + v2.y;
        o.z = v1.z + v2.z; o.w = v1.w + v2.w;
        *(float4*)&sBias[i] = o;
    }
    for (int i = tid; i < 1040; i += NTHR) sFcw[i] = fcw[i];
    sYh[tid] = yh[b * 256 + tid];
    if (tid == 0) sCst[0] = b2[0];
    if (tid < 4)  sCst[4 + tid] = fcb[tid];
    stageK(taskW, taskLdw, Bw, taskK);
    __syncthreads();

    // =======================================================================
    for (int t = 0; t < 64; t++) {
        const unsigned tgt64  = (unsigned)(64 * (t + 1));
        const unsigned tgt128 = (unsigned)(128 * (t + 1));

        // ---- phase A: one GEMM task per block; split S/G arrivals ---------
        {
            stageK(taskA, 512, Ast, taskK);
            __syncthreads();
            unsigned long long acc[4][2];
#pragma unroll
            for (int i = 0; i < 4; i++) { acc[i][0] = 0ull; acc[i][1] = 0ull; }
            mmaK(Ast, Bw, acc, taskK);
            epilogue(acc, taskC, taskLdc, 0);
            __syncthreads();
            if (tid == 0) flag_arrive(taskFlag);
        }

        // ---- phase B1: attention (needs S; overlaps G-GEMM) ---------------
        flag_wait_ge(&g_cntS, tgt64);
        sS[tid] = g_Sp[0][b * 256 + tid] + g_Sp[1][b * 256 + tid]
                + g_Sp[2][b * 256 + tid] + g_Sp[3][b * 256 + tid]
                + g_Sp[4][b * 256 + tid] + g_Sp[5][b * 256 + tid]
                + g_Sp[6][b * 256 + tid] + g_Sp[7][b * 256 + tid];
        __syncthreads();

        // scores + exp (bounded scores: no max pass) + per-warp sums
        {
            const float b2v = sCst[0];
            float wsum = 0.f;
            for (int ww = wid; ww < 64; ww += 8) {
                const float* Pp = &sP[ww * 256];
                float part = 0.f;
#pragma unroll
                for (int j = 0; j < 8; j++) {
                    int e = lane + 32 * j;
                    part += sW2[e] * tanh_fast(Pp[e] + sS[e]);
                }
#pragma unroll
                for (int o = 16; o; o >>= 1) part += __shfl_xor_sync(0xffffffffu, part, o);
                float ev = __expf(part + b2v);
                if (lane == 0) { sAttn[ww] = ev; wsum += ev; }
            }
            if (lane == 0) sWsum[wid] = wsum;
        }
        __syncthreads();

        // context[e] = (1/Z) * sum_w attn[w] * enc[b,w,e]
        {
            float inv = 1.f / (sWsum[0] + sWsum[1] + sWsum[2] + sWsum[3]
                             + sWsum[4] + sWsum[5] + sWsum[6] + sWsum[7]);
            float acc = 0.f;
#pragma unroll 8
            for (int w = 0; w < 64; w++) acc += sAttn[w] * sEnc[w * 256 + tid];
            sCtx[tid] = acc * inv;
        }
        __syncthreads();

        // y_tilde (warps 0-3) || G-flag poll (warp 7)
        if (wid < 4) {
            float acc = 0.f;
            const float* fr = &sFcw[wid * 260];
            for (int e = lane; e < 256; e += 32) acc += fr[e] * sCtx[e];
#pragma unroll
            for (int o = 16; o; o >>= 1) acc += __shfl_xor_sync(0xffffffffu, acc, o);
            if (lane == 0) {
                float yv = 0.f;
#pragma unroll
                for (int f = 0; f < 4; f++) yv += fr[256 + f] * sYh[t * 4 + f];
                sY[wid] = acc + yv + sCst[4 + wid];
            }
        } else if (wid == 7 && lane == 0) {
            flag_poll_ge(&g_cntG, tgt64);
        }
        __syncthreads();

        // ---- phase B2: gates + LSTM cell ----------------------------------
        {
            int j = tid;
            float g[4];
#pragma unroll
            for (int q = 0; q < 4; q++) {
                int d = q * 256 + j;
                float4 wr = *(const float4*)&sWih[d * 4];
                g[q] = g_Gp[0][b * 1024 + d] + g_Gp[1][b * 1024 + d] + sBias[d]
                     + wr.x * sY[0] + wr.y * sY[1] + wr.z * sY[2] + wr.w * sY[3];
            }
            float ig = 1.f / (1.f + expf(-g[0]));
            float fg = 1.f / (1.f + expf(-g[1]));
            float gg = tanhf(g[2]);
            float og = 1.f / (1.f + expf(-g[3]));
            float c_old = g_HC[b * 512 + 256 + j];
            float c_new = fg * c_old + ig * gg;
            float h_new = og * tanhf(c_new);
            g_HC[b * 512 + j]       = h_new;
            g_HC[b * 512 + 256 + j] = c_new;
            if (t == 63) sH[j] = h_new;
        }

        // final output at last step: out[b,:] = fcf([h, ctx])
        if (t == 63) {
            __syncthreads();
            if (wid < 4) {
                float acc = 0.f;
                const float* fr = &fcfw[wid * 512];
                for (int i = lane; i < 512; i += 32) {
                    float v = (i < 256) ? sH[i] : sCtx[i - 256];
                    acc += fr[i] * v;
                }
#pragma unroll
                for (int o = 16; o; o >>= 1) acc += __shfl_xor_sync(0xffffffffu, acc, o);
                if (lane == 0) out[b * 4 + wid] = acc + fcfb[wid];
            }
        }

        // ---- end-of-step: one-hop full sync on h,c ------------------------
        __syncthreads();
        if (tid == 0) flag_arrive(&g_cntH);
        flag_wait_ge(&g_cntH, tgt128);
    }

    // full two-hop barrier once, then reset monotonic counters (replay-safe)
    grid_barrier();
    if (b == 0 && tid == 0) {
        asm volatile("st.relaxed.gpu.global.u32 [%0], %1;" :: "l"(&g_cntP), "r"(0u));
        asm volatile("st.relaxed.gpu.global.u32 [%0], %1;" :: "l"(&g_cntS), "r"(0u));
        asm volatile("st.relaxed.gpu.global.u32 [%0], %1;" :: "l"(&g_cntG), "r"(0u));
        asm volatile("st.relaxed.gpu.global.u32 [%0], %1;" :: "l"(&g_cntH), "r"(0u));
    }
}

// ---------------------------------------------------------------------------
extern "C" void kernel_launch(void* const* d_in, const int* in_sizes, int n_in,
                              void* d_out, int out_size) {
    const float* enc  = (const float*)d_in[0];
    const float* yh   = (const float*)d_in[1];
    const float* w1   = (const float*)d_in[2];
    const float* b1   = (const float*)d_in[3];
    const float* w2   = (const float*)d_in[4];
    const float* b2   = (const float*)d_in[5];
    const float* wih  = (const float*)d_in[6];
    const float* whh  = (const float*)d_in[7];
    const float* bih  = (const float*)d_in[8];
    const float* bhh  = (const float*)d_in[9];
    const float* fcw  = (const float*)d_in[10];
    const float* fcb  = (const float*)d_in[11];
    const float* fcfw = (const float*)d_in[12];
    const float* fcfb = (const float*)d_in[13];
    float* out = (float*)d_out;

    static int configured = 0;
    if (!configured) {
        cudaFuncSetAttribute(decoder_persistent,
                             cudaFuncAttributeMaxDynamicSharedMemorySize, SMEM_BYTES);
        configured = 1;
    }
    decoder_persistent<<<NBLK, NTHR, SMEM_BYTES>>>(
        enc, yh, w1, b1, w2, b2, wih, whh, bih, bhh, fcw, fcb, fcfw, fcfb, out);
}

// round 13
// speedup vs baseline: 1.4301x; 1.0305x over previous
#include <cuda_runtime.h>
#include <stdint.h>
#include <math.h>

#define NBLK 128
#define NTHR 256

// __device__ scratch (allocation-free rule)
__device__ float g_P[128 * 64 * 256];        // P[b,w,e] (8 MB)
__device__ float g_HC[128 * 512];            // [b][0:256]=h, [b][256:512]=c
__device__ float g_Sp[8][128 * 256];         // S kc-partials (K=64 each)
__device__ float g_Gp[2][128 * 1024];        // Ghh kc-partials (K=128 each)
__device__ unsigned g_cntP, g_cntS, g_cntG, g_cntH;   // monotonic flags
__device__ unsigned g_bar_gen, g_bar_cnt;             // final barrier only

// ---- smem float offsets (total 55840 floats = 223360 B) ----
#define F_ENC   0        // 16384
#define F_P     16384    // 16384
#define F_W2    32768    // 256
#define F_WIH   33024    // 4096
#define F_BIAS  37120    // 1024 (bih+bhh)
#define F_FCW   38144    // 1048 (fcw 1040, pad)
#define F_YH    39192    // 256  (yh[b] all steps)
#define F_CONST 39448    // 8    ([0]=b2, [4..7]=fcb)
#define F_SCR   39456    // 16384 (Ast | Bw; overlay in Ast region)
#define SMEM_BYTES (55840 * 4)

// ---------------------------------------------------------------------------
__device__ __forceinline__ float tanh_fast(float x) {
    float y;
    asm("tanh.approx.f32 %0, %1;" : "=f"(y) : "f"(x));
    return y;
}
__device__ __forceinline__ float sigmoid_fast(float x) {
    return fmaf(tanh_fast(0.5f * x), 0.5f, 0.5f);
}
__device__ __forceinline__ unsigned long long pack2(float x, float y) {
    unsigned long long r;
    asm("mov.b64 %0, {%1, %2};" : "=l"(r) : "f"(x), "f"(y));
    return r;
}
__device__ __forceinline__ unsigned long long fma2(unsigned long long a,
                                                   unsigned long long b,
                                                   unsigned long long c) {
    unsigned long long d;
    asm("fma.rn.f32x2 %0, %1, %2, %3;" : "=l"(d) : "l"(a), "l"(b), "l"(c));
    return d;
}
__device__ __forceinline__ float2 unpack2(unsigned long long v) {
    float lo, hi;
    asm("mov.b64 {%0, %1}, %2;" : "=f"(lo), "=f"(hi) : "l"(v));
    return make_float2(lo, hi);
}

// fire-and-forget arrival (tid0, after __syncthreads)
__device__ __forceinline__ void flag_arrive(unsigned* p) {
    asm volatile("red.release.gpu.global.add.u32 [%0], %1;" :: "l"(p), "r"(1u));
}
// raw poll (no syncthreads) — caller supplies the block-wide sync
__device__ __forceinline__ void flag_poll_ge(unsigned* p, unsigned target) {
    unsigned v;
    do {
        asm volatile("ld.acquire.gpu.global.u32 %0, [%1];" : "=r"(v) : "l"(p));
    } while (v < target);
}
// block-wide wait: tid0 polls, then syncthreads propagates
__device__ __forceinline__ void flag_wait_ge(unsigned* p, unsigned target) {
    if (threadIdx.x == 0) flag_poll_ge(p, target);
    __syncthreads();
}

// two-hop barrier, used ONCE after the loop (reset safety)
__device__ __forceinline__ void grid_barrier() {
    __syncthreads();
    if (threadIdx.x == 0) {
        unsigned gen;
        asm volatile("ld.acquire.gpu.global.u32 %0, [%1];" : "=r"(gen) : "l"(&g_bar_gen));
        if (blockIdx.x == 0) {
            unsigned c;
            do {
                asm volatile("ld.acquire.gpu.global.u32 %0, [%1];" : "=r"(c) : "l"(&g_bar_cnt));
            } while (c != NBLK - 1);
            asm volatile("st.relaxed.gpu.global.u32 [%0], %1;" :: "l"(&g_bar_cnt), "r"(0u));
            asm volatile("st.release.gpu.global.u32 [%0], %1;" :: "l"(&g_bar_gen), "r"(gen + 1u));
        } else {
            asm volatile("red.release.gpu.global.add.u32 [%0], %1;" :: "l"(&g_bar_cnt), "r"(1u));
            unsigned g2;
            do {
                asm volatile("ld.acquire.gpu.global.u32 %0, [%1];" : "=r"(g2) : "l"(&g_bar_gen));
            } while (g2 == gen);
        }
    }
    __syncthreads();
}

// ---------------------------------------------------------------------------
// Stage 64 rows x K cols of X (row-major ldx) into Xst[k][r] (stride 64).
__device__ __forceinline__ void stageK(const float* __restrict__ Xp, int ldx,
                                       float* __restrict__ Xst, int K) {
    const int tid = threadIdx.x;
    const int r  = tid & 63;
    const int kg = tid >> 6;
    const int nq = K >> 4;
#pragma unroll
    for (int q = 0; q < nq; q++) {
        int k4 = (kg + q * 4) << 2;
        float4 v = *(const float4*)(Xp + r * ldx + k4);
        Xst[(k4 + 0) * 64 + r] = v.x;
        Xst[(k4 + 1) * 64 + r] = v.y;
        Xst[(k4 + 2) * 64 + r] = v.z;
        Xst[(k4 + 3) * 64 + r] = v.w;
    }
}

// 64x64 x K accumulate with packed f32x2 FMA. acc[4][2] packed pairs.
__device__ __forceinline__ void mmaK(const float* __restrict__ Ast,
                                     const float* __restrict__ Bst,
                                     unsigned long long acc[4][2], int K) {
    const int ty = threadIdx.x >> 4, tx = threadIdx.x & 15;
#pragma unroll 8
    for (int k = 0; k < K; k++) {
        float4 a = *(const float4*)&Ast[k * 64 + ty * 4];
        ulonglong2 b = *(const ulonglong2*)&Bst[k * 64 + tx * 4];
        unsigned long long a0 = pack2(a.x, a.x);
        unsigned long long a1 = pack2(a.y, a.y);
        unsigned long long a2 = pack2(a.z, a.z);
        unsigned long long a3 = pack2(a.w, a.w);
        acc[0][0] = fma2(a0, b.x, acc[0][0]); acc[0][1] = fma2(a0, b.y, acc[0][1]);
        acc[1][0] = fma2(a1, b.x, acc[1][0]); acc[1][1] = fma2(a1, b.y, acc[1][1]);
        acc[2][0] = fma2(a2, b.x, acc[2][0]); acc[2][1] = fma2(a2, b.y, acc[2][1]);
        acc[3][0] = fma2(a3, b.x, acc[3][0]); acc[3][1] = fma2(a3, b.y, acc[3][1]);
    }
}

__device__ __forceinline__ void epilogue(unsigned long long acc[4][2],
                                         float* __restrict__ Cptr, int ldc,
                                         const float* __restrict__ bias) {
    const int ty = threadIdx.x >> 4, tx = threadIdx.x & 15;
    float4 bb = make_float4(0.f, 0.f, 0.f, 0.f);
    if (bias) bb = *(const float4*)&bias[tx * 4];
#pragma unroll
    for (int i = 0; i < 4; i++) {
        float2 lo = unpack2(acc[i][0]);
        float2 hi = unpack2(acc[i][1]);
        float4 o;
        o.x = lo.x + bb.x; o.y = lo.y + bb.y;
        o.z = hi.x + bb.z; o.w = hi.y + bb.w;
        *(float4*)&Cptr[(ty * 4 + i) * ldc + tx * 4] = o;
    }
}

// Full tile GEMM (stages both operands) for the one-time P precompute.
__device__ __forceinline__ void gemm64_full(
    const float* __restrict__ Aptr, int lda,
    const float* __restrict__ Bptr, int ldb,
    float* __restrict__ Cptr, int ldc,
    int nchunk, const float* __restrict__ bias,
    float* __restrict__ Ast, float* __restrict__ Bst)
{
    unsigned long long acc[4][2];
#pragma unroll
    for (int i = 0; i < 4; i++) { acc[i][0] = 0ull; acc[i][1] = 0ull; }
    for (int c = 0; c < nchunk; c++) {
        stageK(Aptr + c * 128, lda, Ast, 128);
        stageK(Bptr + c * 128, ldb, Bst, 128);
        __syncthreads();
        mmaK(Ast, Bst, acc, 128);
        __syncthreads();
    }
    epilogue(acc, Cptr, ldc, bias);
}

// ---------------------------------------------------------------------------
__global__ __launch_bounds__(NTHR, 1)
void decoder_persistent(
    const float* __restrict__ enc,  const float* __restrict__ yh,
    const float* __restrict__ w1,   const float* __restrict__ b1,
    const float* __restrict__ w2,   const float* __restrict__ b2,
    const float* __restrict__ wih,  const float* __restrict__ whh,
    const float* __restrict__ bih,  const float* __restrict__ bhh,
    const float* __restrict__ fcw,  const float* __restrict__ fcb,
    const float* __restrict__ fcfw, const float* __restrict__ fcfb,
    float* __restrict__ out)
{
    extern __shared__ float sm[];
    float* sEnc  = sm + F_ENC;
    float* sP    = sm + F_P;
    float* sW2   = sm + F_W2;
    float* sWih  = sm + F_WIH;
    float* sBias = sm + F_BIAS;
    float* sFcw  = sm + F_FCW;
    float* sYh   = sm + F_YH;
    float* sCst  = sm + F_CONST;
    float* scr   = sm + F_SCR;
    float* Ast   = scr;           // up to 8192 floats (K<=128)
    float* Bw    = scr + 8192;    // persistent weight tile
    // phase-B overlay (inside Ast region; Bw untouched)
    float* sS    = scr;
    float* sCtx  = scr + 256;
    float* sAttn = scr + 576;
    float* sWsum = scr + 640;
    float* sY    = scr + 656;
    float* sH    = scr + 672;     // 672..927
    float* sGG   = scr + 1024;    // 1024..2047 (gate partial sums)

    const int b   = blockIdx.x;
    const int tid = threadIdx.x;
    const int lane = tid & 31, wid = tid >> 5;

    // ---- init: zero h,c for my batch ----
    g_HC[b * 512 + tid]       = 0.f;
    g_HC[b * 512 + 256 + tid] = 0.f;

    // ---- precompute P = enc · W1_e^T + b1 : 512 tiles of 64x64x256 ----
    for (int q = 0; q < 4; q++) {
        int tile = b + NBLK * q;           // mt 0..127, nt 0..3
        int mt = tile >> 2, nt = tile & 3;
        gemm64_full(enc + mt * 64 * 256, 256,
                    w1 + nt * 64 * 768 + 512, 768,
                    g_P + mt * 64 * 256 + nt * 64, 256,
                    2, b1 + nt * 64, Ast, Bw);
    }
    __syncthreads();
    if (tid == 0) flag_arrive(&g_cntP);
    flag_wait_ge(&g_cntP, NBLK);

    // ---- decode my fixed per-step GEMM task ----
    const float* taskA; const float* taskW;
    float* taskC; int taskLdw, taskLdc, taskK;
    unsigned* taskFlag;
    if (b < 64) {
        int kc = b & 7, nt = (b >> 3) & 3, mt = b >> 5;
        taskA = g_HC + mt * 64 * 512 + kc * 64;
        taskW = w1 + nt * 64 * 768 + kc * 64;  taskLdw = 768;
        taskC = g_Sp[kc] + mt * 64 * 256 + nt * 64;  taskLdc = 256;
        taskK = 64;  taskFlag = &g_cntS;
    } else {
        int g = b - 64;
        int kc = g >> 5, mt = (g >> 4) & 1, nt = g & 15;
        taskA = g_HC + mt * 64 * 512 + kc * 128;
        taskW = whh + nt * 64 * 256 + kc * 128;  taskLdw = 256;
        taskC = g_Gp[kc] + mt * 64 * 1024 + nt * 64;  taskLdc = 1024;
        taskK = 128;  taskFlag = &g_cntG;
    }

    // ---- one-time staging: per-batch data + invariant weights ----
    for (int i = tid * 4; i < 16384; i += NTHR * 4) {
        *(float4*)&sEnc[i] = *(const float4*)&enc[b * 16384 + i];
        *(float4*)&sP[i]   = *(const float4*)&g_P[b * 16384 + i];
    }
    sW2[tid] = w2[tid];
    for (int i = tid * 4; i < 4096; i += NTHR * 4)
        *(float4*)&sWih[i] = *(const float4*)&wih[i];
    {
        int i = tid * 4;
        float4 v1 = *(const float4*)&bih[i];
        float4 v2 = *(const float4*)&bhh[i];
        float4 o; o.x = v1.x + v2.x; o.y = v1.y + v2.y;
        o.z = v1.z + v2.z; o.w = v1.w + v2.w;
        *(float4*)&sBias[i] = o;
    }
    for (int i = tid; i < 1040; i += NTHR) sFcw[i] = fcw[i];
    sYh[tid] = yh[b * 256 + tid];
    if (tid == 0) sCst[0] = b2[0];
    if (tid < 4)  sCst[4 + tid] = fcb[tid];
    stageK(taskW, taskLdw, Bw, taskK);
    __syncthreads();

    // =======================================================================
    for (int t = 0; t < 64; t++) {
        const unsigned tgt64  = (unsigned)(64 * (t + 1));
        const unsigned tgt128 = (unsigned)(128 * (t + 1));

        // ---- phase A: one GEMM task per block; split S/G arrivals ---------
        {
            stageK(taskA, 512, Ast, taskK);
            __syncthreads();
            unsigned long long acc[4][2];
#pragma unroll
            for (int i = 0; i < 4; i++) { acc[i][0] = 0ull; acc[i][1] = 0ull; }
            mmaK(Ast, Bw, acc, taskK);
            epilogue(acc, taskC, taskLdc, 0);
            __syncthreads();
            if (tid == 0) flag_arrive(taskFlag);
        }

        // ---- phase B1: attention (needs S; overlaps G-GEMM) ---------------
        flag_wait_ge(&g_cntS, tgt64);
        sS[tid] = g_Sp[0][b * 256 + tid] + g_Sp[1][b * 256 + tid]
                + g_Sp[2][b * 256 + tid] + g_Sp[3][b * 256 + tid]
                + g_Sp[4][b * 256 + tid] + g_Sp[5][b * 256 + tid]
                + g_Sp[6][b * 256 + tid] + g_Sp[7][b * 256 + tid];
        __syncthreads();

        // scores + exp, sS/w2 register-cached (1 LDS per element, not 3)
        {
            float sreg[8], wreg[8];
#pragma unroll
            for (int j = 0; j < 8; j++) {
                int e = lane + 32 * j;
                sreg[j] = sS[e];
                wreg[j] = sW2[e];
            }
            const float b2v = sCst[0];
            float wsum = 0.f;
            for (int ww = wid; ww < 64; ww += 8) {
                const float* Pp = &sP[ww * 256];
                float part = 0.f;
#pragma unroll
                for (int j = 0; j < 8; j++) {
                    int e = lane + 32 * j;
                    part += wreg[j] * tanh_fast(Pp[e] + sreg[j]);
                }
#pragma unroll
                for (int o = 16; o; o >>= 1) part += __shfl_xor_sync(0xffffffffu, part, o);
                float ev = __expf(part + b2v);
                if (lane == 0) { sAttn[ww] = ev; wsum += ev; }
            }
            if (lane == 0) sWsum[wid] = wsum;
        }
        __syncthreads();

        // context[e] = (1/Z) * sum_w attn[w] * enc[b,w,e]
        {
            float inv = 1.f / (sWsum[0] + sWsum[1] + sWsum[2] + sWsum[3]
                             + sWsum[4] + sWsum[5] + sWsum[6] + sWsum[7]);
            float acc = 0.f;
#pragma unroll 8
            for (int w = 0; w < 64; w++) acc += sAttn[w] * sEnc[w * 256 + tid];
            sCtx[tid] = acc * inv;
        }
        __syncthreads();

        // y_tilde (warps 0-3) || G-wait + g_Gp prefetch to smem (warps 4-7)
        if (wid < 4) {
            float acc = 0.f;
            const float* fr = &sFcw[wid * 260];
            for (int e = lane; e < 256; e += 32) acc += fr[e] * sCtx[e];
#pragma unroll
            for (int o = 16; o; o >>= 1) acc += __shfl_xor_sync(0xffffffffu, acc, o);
            if (lane == 0) {
                float yv = 0.f;
#pragma unroll
                for (int f = 0; f < 4; f++) yv += fr[256 + f] * sYh[t * 4 + f];
                sY[wid] = acc + yv + sCst[4 + wid];
            }
        } else {
            if (wid == 4 && lane == 0) flag_poll_ge(&g_cntG, tgt64);
            asm volatile("bar.sync 1, 128;" ::: "memory");   // warps 4-7 only
            int i = (tid - 128) * 8;                         // 128 thr x 8 = 1024
            float4 a0 = *(const float4*)&g_Gp[0][b * 1024 + i];
            float4 a1 = *(const float4*)&g_Gp[0][b * 1024 + i + 4];
            float4 c0 = *(const float4*)&g_Gp[1][b * 1024 + i];
            float4 c1 = *(const float4*)&g_Gp[1][b * 1024 + i + 4];
            float4 o0, o1;
            o0.x = a0.x + c0.x; o0.y = a0.y + c0.y; o0.z = a0.z + c0.z; o0.w = a0.w + c0.w;
            o1.x = a1.x + c1.x; o1.y = a1.y + c1.y; o1.z = a1.z + c1.z; o1.w = a1.w + c1.w;
            *(float4*)&sGG[i]     = o0;
            *(float4*)&sGG[i + 4] = o1;
        }
        __syncthreads();

        // ---- phase B2: gates + LSTM cell (all smem, HW transcendentals) ---
        {
            int j = tid;
            float g[4];
#pragma unroll
            for (int q = 0; q < 4; q++) {
                int d = q * 256 + j;
                float4 wr = *(const float4*)&sWih[d * 4];
                g[q] = sGG[d] + sBias[d]
                     + wr.x * sY[0] + wr.y * sY[1] + wr.z * sY[2] + wr.w * sY[3];
            }
            float ig = sigmoid_fast(g[0]);
            float fg = sigmoid_fast(g[1]);
            float gg = tanh_fast(g[2]);
            float og = sigmoid_fast(g[3]);
            float c_old = g_HC[b * 512 + 256 + j];
            float c_new = fg * c_old + ig * gg;
            float h_new = og * tanh_fast(c_new);
            g_HC[b * 512 + j]       = h_new;
            g_HC[b * 512 + 256 + j] = c_new;
            if (t == 63) sH[j] = h_new;
        }

        // final output at last step: out[b,:] = fcf([h, ctx])
        if (t == 63) {
            __syncthreads();
            if (wid < 4) {
                float acc = 0.f;
                const float* fr = &fcfw[wid * 512];
                for (int i = lane; i < 512; i += 32) {
                    float v = (i < 256) ? sH[i] : sCtx[i - 256];
                    acc += fr[i] * v;
                }
#pragma unroll
                for (int o = 16; o; o >>= 1) acc += __shfl_xor_sync(0xffffffffu, acc, o);
                if (lane == 0) out[b * 4 + wid] = acc + fcfb[wid];
            }
        }

        // ---- end-of-step: one-hop full sync on h,c ------------------------
        __syncthreads();
        if (tid == 0) flag_arrive(&g_cntH);
        flag_wait_ge(&g_cntH, tgt128);
    }

    // full two-hop barrier once, then reset monotonic counters (replay-safe)
    grid_barrier();
    if (b == 0 && tid == 0) {
        asm volatile("st.relaxed.gpu.global.u32 [%0], %1;" :: "l"(&g_cntP), "r"(0u));
        asm volatile("st.relaxed.gpu.global.u32 [%0], %1;" :: "l"(&g_cntS), "r"(0u));
        asm volatile("st.relaxed.gpu.global.u32 [%0], %1;" :: "l"(&g_cntG), "r"(0u));
        asm volatile("st.relaxed.gpu.global.u32 [%0], %1;" :: "l"(&g_cntH), "r"(0u));
    }
}

// ---------------------------------------------------------------------------
extern "C" void kernel_launch(void* const* d_in, const int* in_sizes, int n_in,
                              void* d_out, int out_size) {
    const float* enc  = (const float*)d_in[0];
    const float* yh   = (const float*)d_in[1];
    const float* w1   = (const float*)d_in[2];
    const float* b1   = (const float*)d_in[3];
    const float* w2   = (const float*)d_in[4];
    const float* b2   = (const float*)d_in[5];
    const float* wih  = (const float*)d_in[6];
    const float* whh  = (const float*)d_in[7];
    const float* bih  = (const float*)d_in[8];
    const float* bhh  = (const float*)d_in[9];
    const float* fcw  = (const float*)d_in[10];
    const float* fcb  = (const float*)d_in[11];
    const float* fcfw = (const float*)d_in[12];
    const float* fcfb = (const float*)d_in[13];
    float* out = (float*)d_out;

    static int configured = 0;
    if (!configured) {
        cudaFuncSetAttribute(decoder_persistent,
                             cudaFuncAttributeMaxDynamicSharedMemorySize, SMEM_BYTES);
        configured = 1;
    }
    decoder_persistent<<<NBLK, NTHR, SMEM_BYTES>>>(
        enc, yh, w1, b1, w2, b2, wih, whh, bih, bhh, fcw, fcb, fcfw, fcfb, out);
}

// round 14
// speedup vs baseline: 1.4542x; 1.0168x over previous
#include <cuda_runtime.h>
#include <stdint.h>
#include <math.h>

#define NBLK 128
#define NTHR 256

// __device__ scratch (allocation-free rule)
__device__ float g_P[128 * 64 * 256];        // P[b,w,e] (8 MB)
__device__ float g_HC[128 * 512];            // [b][0:256]=h, [b][256:512]=c
__device__ float g_Sp[16][128 * 256];        // S kc-partials (K=32 each)
__device__ float g_Gp[4][128 * 1024];        // Ghh kc-partials (K=64 each)
__device__ unsigned g_cntP, g_cntS, g_cntG, g_cntH;   // monotonic flags
__device__ unsigned g_bar_gen, g_bar_cnt;             // final barrier only

// ---- smem float offsets (total 55840 floats = 223360 B) ----
#define F_ENC   0        // 16384
#define F_P     16384    // 16384
#define F_W2    32768    // 256
#define F_WIH   33024    // 4096
#define F_BIAS  37120    // 1024 (bih+bhh)
#define F_FCW   38144    // 1048 (fcw 1040, pad)
#define F_YH    39192    // 256  (yh[b] all steps)
#define F_CONST 39448    // 8    ([0]=b2, [4..7]=fcb)
#define F_SCR   39456    // 16384: init Ast|Bst; steady: Ast/overlay | BwS | BwG
#define SMEM_BYTES (55840 * 4)

// steady-state scratch sublayout (floats, relative to F_SCR)
#define SC_AST  0        // 4096 (Ast, K<=64; phase-B overlay lives here too)
#define SC_BWS  4096     // 2048 (persistent S weight tile 64x32)
#define SC_BWG  6144     // 4096 (persistent G weight tile 64x64)

// ---------------------------------------------------------------------------
__device__ __forceinline__ float tanh_fast(float x) {
    float y;
    asm("tanh.approx.f32 %0, %1;" : "=f"(y) : "f"(x));
    return y;
}
__device__ __forceinline__ float sigmoid_fast(float x) {
    return fmaf(tanh_fast(0.5f * x), 0.5f, 0.5f);
}
__device__ __forceinline__ unsigned long long pack2(float x, float y) {
    unsigned long long r;
    asm("mov.b64 %0, {%1, %2};" : "=l"(r) : "f"(x), "f"(y));
    return r;
}
__device__ __forceinline__ unsigned long long fma2(unsigned long long a,
                                                   unsigned long long b,
                                                   unsigned long long c) {
    unsigned long long d;
    asm("fma.rn.f32x2 %0, %1, %2, %3;" : "=l"(d) : "l"(a), "l"(b), "l"(c));
    return d;
}
__device__ __forceinline__ float2 unpack2(unsigned long long v) {
    float lo, hi;
    asm("mov.b64 {%0, %1}, %2;" : "=f"(lo), "=f"(hi) : "l"(v));
    return make_float2(lo, hi);
}

// fire-and-forget arrival (tid0, after __syncthreads)
__device__ __forceinline__ void flag_arrive(unsigned* p) {
    asm volatile("red.release.gpu.global.add.u32 [%0], %1;" :: "l"(p), "r"(1u));
}
__device__ __forceinline__ void flag_poll_ge(unsigned* p, unsigned target) {
    unsigned v;
    do {
        asm volatile("ld.acquire.gpu.global.u32 %0, [%1];" : "=r"(v) : "l"(p));
    } while (v < target);
}
__device__ __forceinline__ void flag_wait_ge(unsigned* p, unsigned target) {
    if (threadIdx.x == 0) flag_poll_ge(p, target);
    __syncthreads();
}

// two-hop barrier, used ONCE after the loop (reset safety)
__device__ __forceinline__ void grid_barrier() {
    __syncthreads();
    if (threadIdx.x == 0) {
        unsigned gen;
        asm volatile("ld.acquire.gpu.global.u32 %0, [%1];" : "=r"(gen) : "l"(&g_bar_gen));
        if (blockIdx.x == 0) {
            unsigned c;
            do {
                asm volatile("ld.acquire.gpu.global.u32 %0, [%1];" : "=r"(c) : "l"(&g_bar_cnt));
            } while (c != NBLK - 1);
            asm volatile("st.relaxed.gpu.global.u32 [%0], %1;" :: "l"(&g_bar_cnt), "r"(0u));
            asm volatile("st.release.gpu.global.u32 [%0], %1;" :: "l"(&g_bar_gen), "r"(gen + 1u));
        } else {
            asm volatile("red.release.gpu.global.add.u32 [%0], %1;" :: "l"(&g_bar_cnt), "r"(1u));
            unsigned g2;
            do {
                asm volatile("ld.acquire.gpu.global.u32 %0, [%1];" : "=r"(g2) : "l"(&g_bar_gen));
            } while (g2 == gen);
        }
    }
    __syncthreads();
}

// ---------------------------------------------------------------------------
// Stage 64 rows x K cols of X (row-major ldx) into Xst[k][r] (stride 64).
__device__ __forceinline__ void stageK(const float* __restrict__ Xp, int ldx,
                                       float* __restrict__ Xst, int K) {
    const int tid = threadIdx.x;
    const int r  = tid & 63;
    const int kg = tid >> 6;
    const int nq = K >> 4;
#pragma unroll
    for (int q = 0; q < nq; q++) {
        int k4 = (kg + q * 4) << 2;
        float4 v = *(const float4*)(Xp + r * ldx + k4);
        Xst[(k4 + 0) * 64 + r] = v.x;
        Xst[(k4 + 1) * 64 + r] = v.y;
        Xst[(k4 + 2) * 64 + r] = v.z;
        Xst[(k4 + 3) * 64 + r] = v.w;
    }
}

// 64x64 x K accumulate with packed f32x2 FMA. acc[4][2] packed pairs.
__device__ __forceinline__ void mmaK(const float* __restrict__ Ast,
                                     const float* __restrict__ Bst,
                                     unsigned long long acc[4][2], int K) {
    const int ty = threadIdx.x >> 4, tx = threadIdx.x & 15;
#pragma unroll 8
    for (int k = 0; k < K; k++) {
        float4 a = *(const float4*)&Ast[k * 64 + ty * 4];
        ulonglong2 b = *(const ulonglong2*)&Bst[k * 64 + tx * 4];
        unsigned long long a0 = pack2(a.x, a.x);
        unsigned long long a1 = pack2(a.y, a.y);
        unsigned long long a2 = pack2(a.z, a.z);
        unsigned long long a3 = pack2(a.w, a.w);
        acc[0][0] = fma2(a0, b.x, acc[0][0]); acc[0][1] = fma2(a0, b.y, acc[0][1]);
        acc[1][0] = fma2(a1, b.x, acc[1][0]); acc[1][1] = fma2(a1, b.y, acc[1][1]);
        acc[2][0] = fma2(a2, b.x, acc[2][0]); acc[2][1] = fma2(a2, b.y, acc[2][1]);
        acc[3][0] = fma2(a3, b.x, acc[3][0]); acc[3][1] = fma2(a3, b.y, acc[3][1]);
    }
}

__device__ __forceinline__ void epilogue(unsigned long long acc[4][2],
                                         float* __restrict__ Cptr, int ldc,
                                         const float* __restrict__ bias) {
    const int ty = threadIdx.x >> 4, tx = threadIdx.x & 15;
    float4 bb = make_float4(0.f, 0.f, 0.f, 0.f);
    if (bias) bb = *(const float4*)&bias[tx * 4];
#pragma unroll
    for (int i = 0; i < 4; i++) {
        float2 lo = unpack2(acc[i][0]);
        float2 hi = unpack2(acc[i][1]);
        float4 o;
        o.x = lo.x + bb.x; o.y = lo.y + bb.y;
        o.z = hi.x + bb.z; o.w = hi.y + bb.w;
        *(float4*)&Cptr[(ty * 4 + i) * ldc + tx * 4] = o;
    }
}

// Full tile GEMM (stages both operands) for the one-time P precompute.
__device__ __forceinline__ void gemm64_full(
    const float* __restrict__ Aptr, int lda,
    const float* __restrict__ Bptr, int ldb,
    float* __restrict__ Cptr, int ldc,
    int nchunk, const float* __restrict__ bias,
    float* __restrict__ Ast, float* __restrict__ Bst)
{
    unsigned long long acc[4][2];
#pragma unroll
    for (int i = 0; i < 4; i++) { acc[i][0] = 0ull; acc[i][1] = 0ull; }
    for (int c = 0; c < nchunk; c++) {
        stageK(Aptr + c * 128, lda, Ast, 128);
        stageK(Bptr + c * 128, ldb, Bst, 128);
        __syncthreads();
        mmaK(Ast, Bst, acc, 128);
        __syncthreads();
    }
    epilogue(acc, Cptr, ldc, bias);
}

// ---------------------------------------------------------------------------
__global__ __launch_bounds__(NTHR, 1)
void decoder_persistent(
    const float* __restrict__ enc,  const float* __restrict__ yh,
    const float* __restrict__ w1,   const float* __restrict__ b1,
    const float* __restrict__ w2,   const float* __restrict__ b2,
    const float* __restrict__ wih,  const float* __restrict__ whh,
    const float* __restrict__ bih,  const float* __restrict__ bhh,
    const float* __restrict__ fcw,  const float* __restrict__ fcb,
    const float* __restrict__ fcfw, const float* __restrict__ fcfb,
    float* __restrict__ out)
{
    extern __shared__ float sm[];
    float* sEnc  = sm + F_ENC;
    float* sP    = sm + F_P;
    float* sW2   = sm + F_W2;
    float* sWih  = sm + F_WIH;
    float* sBias = sm + F_BIAS;
    float* sFcw  = sm + F_FCW;
    float* sYh   = sm + F_YH;
    float* sCst  = sm + F_CONST;
    float* scr   = sm + F_SCR;
    float* Ast   = scr + SC_AST;   // 4096 floats (K<=64)
    float* BwS   = scr + SC_BWS;   // persistent S weight tile (64x32)
    float* BwG   = scr + SC_BWG;   // persistent G weight tile (64x64)
    // phase-B overlay (inside Ast region; BwS/BwG untouched)
    float* sS    = scr;
    float* sCtx  = scr + 256;
    float* sAttn = scr + 576;
    float* sWsum = scr + 640;
    float* sY    = scr + 656;
    float* sH    = scr + 672;      // 672..927
    float* sGG   = scr + 1024;     // 1024..2047 (gate partial sums)

    const int b   = blockIdx.x;
    const int tid = threadIdx.x;
    const int lane = tid & 31, wid = tid >> 5;

    // ---- init: zero h,c for my batch ----
    g_HC[b * 512 + tid]       = 0.f;
    g_HC[b * 512 + 256 + tid] = 0.f;

    // ---- precompute P = enc · W1_e^T + b1 : 512 tiles of 64x64x256 ----
    // (init uses scr[0..16383] as Ast|Bst; persistent tiles staged after)
    for (int q = 0; q < 4; q++) {
        int tile = b + NBLK * q;           // mt 0..127, nt 0..3
        int mt = tile >> 2, nt = tile & 3;
        gemm64_full(enc + mt * 64 * 256, 256,
                    w1 + nt * 64 * 768 + 512, 768,
                    g_P + mt * 64 * 256 + nt * 64, 256,
                    2, b1 + nt * 64, scr, scr + 8192);
    }
    __syncthreads();
    if (tid == 0) flag_arrive(&g_cntP);
    flag_wait_ge(&g_cntP, NBLK);

    // ---- decode my two fixed per-step GEMM tasks ----
    // S: b = kc*8 + mt*4 + nt  (kc 0..15, mt 0..1, nt 0..3), K=32
    // G: b = kc*32 + mt*16 + nt (kc 0..3, mt 0..1, nt 0..15), K=64
    const float *sA, *sW, *gA, *gW;
    float *sC, *gC;
    {
        int kc = b >> 3, mt = (b >> 2) & 1, nt = b & 3;
        sA = g_HC + mt * 64 * 512 + kc * 32;
        sW = w1 + nt * 64 * 768 + kc * 32;
        sC = g_Sp[kc] + mt * 64 * 256 + nt * 64;
    }
    {
        int kc = b >> 5, mt = (b >> 4) & 1, nt = b & 15;
        gA = g_HC + mt * 64 * 512 + kc * 64;
        gW = whh + nt * 64 * 256 + kc * 64;
        gC = g_Gp[kc] + mt * 64 * 1024 + nt * 64;
    }

    // ---- one-time staging: per-batch data + invariant weights ----
    for (int i = tid * 4; i < 16384; i += NTHR * 4) {
        *(float4*)&sEnc[i] = *(const float4*)&enc[b * 16384 + i];
        *(float4*)&sP[i]   = *(const float4*)&g_P[b * 16384 + i];
    }
    sW2[tid] = w2[tid];
    for (int i = tid * 4; i < 4096; i += NTHR * 4)
        *(float4*)&sWih[i] = *(const float4*)&wih[i];
    {
        int i = tid * 4;
        float4 v1 = *(const float4*)&bih[i];
        float4 v2 = *(const float4*)&bhh[i];
        float4 o; o.x = v1.x + v2.x; o.y = v1.y + v2.y;
        o.z = v1.z + v2.z; o.w = v1.w + v2.w;
        *(float4*)&sBias[i] = o;
    }
    for (int i = tid; i < 1040; i += NTHR) sFcw[i] = fcw[i];
    sYh[tid] = yh[b * 256 + tid];
    if (tid == 0) sCst[0] = b2[0];
    if (tid < 4)  sCst[4 + tid] = fcb[tid];
    stageK(sW, 768, BwS, 32);
    stageK(gW, 256, BwG, 64);
    __syncthreads();

    // =======================================================================
    for (int t = 0; t < 64; t++) {
        const unsigned tgt = (unsigned)(128 * (t + 1));

        // ---- phase A1: S task (K=32, ~1024 cyc) ---------------------------
        {
            stageK(sA, 512, Ast, 32);
            __syncthreads();
            unsigned long long acc[4][2];
#pragma unroll
            for (int i = 0; i < 4; i++) { acc[i][0] = 0ull; acc[i][1] = 0ull; }
            mmaK(Ast, BwS, acc, 32);
            epilogue(acc, sC, 256, 0);
            __syncthreads();
            if (tid == 0) flag_arrive(&g_cntS);
        }

        // ---- phase A2: G task (K=64, ~2048 cyc; covered by B1) ------------
        {
            stageK(gA, 512, Ast, 64);
            __syncthreads();
            unsigned long long acc[4][2];
#pragma unroll
            for (int i = 0; i < 4; i++) { acc[i][0] = 0ull; acc[i][1] = 0ull; }
            mmaK(Ast, BwG, acc, 64);
            epilogue(acc, gC, 1024, 0);
            __syncthreads();
            if (tid == 0) flag_arrive(&g_cntG);
        }

        // ---- phase B1: attention (needs all S) ----------------------------
        flag_wait_ge(&g_cntS, tgt);
        {
            float a0 = 0.f;
#pragma unroll
            for (int kc = 0; kc < 16; kc++) a0 += g_Sp[kc][b * 256 + tid];
            sS[tid] = a0;
        }
        __syncthreads();

        // scores + exp, sS/w2 register-cached
        {
            float sreg[8], wreg[8];
#pragma unroll
            for (int j = 0; j < 8; j++) {
                int e = lane + 32 * j;
                sreg[j] = sS[e];
                wreg[j] = sW2[e];
            }
            const float b2v = sCst[0];
            float wsum = 0.f;
            for (int ww = wid; ww < 64; ww += 8) {
                const float* Pp = &sP[ww * 256];
                float part = 0.f;
#pragma unroll
                for (int j = 0; j < 8; j++) {
                    int e = lane + 32 * j;
                    part += wreg[j] * tanh_fast(Pp[e] + sreg[j]);
                }
#pragma unroll
                for (int o = 16; o; o >>= 1) part += __shfl_xor_sync(0xffffffffu, part, o);
                float ev = __expf(part + b2v);
                if (lane == 0) { sAttn[ww] = ev; wsum += ev; }
            }
            if (lane == 0) sWsum[wid] = wsum;
        }
        __syncthreads();

        // context[e] = (1/Z) * sum_w attn[w] * enc[b,w,e]
        {
            float inv = 1.f / (sWsum[0] + sWsum[1] + sWsum[2] + sWsum[3]
                             + sWsum[4] + sWsum[5] + sWsum[6] + sWsum[7]);
            float acc = 0.f;
#pragma unroll 8
            for (int w = 0; w < 64; w++) acc += sAttn[w] * sEnc[w * 256 + tid];
            sCtx[tid] = acc * inv;
        }
        __syncthreads();

        // y_tilde (warps 0-3) || G-wait + g_Gp prefetch to smem (warps 4-7)
        if (wid < 4) {
            float acc = 0.f;
            const float* fr = &sFcw[wid * 260];
            for (int e = lane; e < 256; e += 32) acc += fr[e] * sCtx[e];
#pragma unroll
            for (int o = 16; o; o >>= 1) acc += __shfl_xor_sync(0xffffffffu, acc, o);
            if (lane == 0) {
                float yv = 0.f;
#pragma unroll
                for (int f = 0; f < 4; f++) yv += fr[256 + f] * sYh[t * 4 + f];
                sY[wid] = acc + yv + sCst[4 + wid];
            }
        } else {
            if (wid == 4 && lane == 0) flag_poll_ge(&g_cntG, tgt);
            asm volatile("bar.sync 1, 128;" ::: "memory");   // warps 4-7 only
            int i = (tid - 128) * 8;                         // 128 thr x 8 = 1024
            float4 o0 = make_float4(0.f, 0.f, 0.f, 0.f);
            float4 o1 = make_float4(0.f, 0.f, 0.f, 0.f);
#pragma unroll
            for (int kc = 0; kc < 4; kc++) {
                float4 a0 = *(const float4*)&g_Gp[kc][b * 1024 + i];
                float4 a1 = *(const float4*)&g_Gp[kc][b * 1024 + i + 4];
                o0.x += a0.x; o0.y += a0.y; o0.z += a0.z; o0.w += a0.w;
                o1.x += a1.x; o1.y += a1.y; o1.z += a1.z; o1.w += a1.w;
            }
            *(float4*)&sGG[i]     = o0;
            *(float4*)&sGG[i + 4] = o1;
        }
        __syncthreads();

        // ---- phase B2: gates + LSTM cell (all smem, HW transcendentals) ---
        {
            int j = tid;
            float g[4];
#pragma unroll
            for (int q = 0; q < 4; q++) {
                int d = q * 256 + j;
                float4 wr = *(const float4*)&sWih[d * 4];
                g[q] = sGG[d] + sBias[d]
                     + wr.x * sY[0] + wr.y * sY[1] + wr.z * sY[2] + wr.w * sY[3];
            }
            float ig = sigmoid_fast(g[0]);
            float fg = sigmoid_fast(g[1]);
            float gg = tanh_fast(g[2]);
            float og = sigmoid_fast(g[3]);
            float c_old = g_HC[b * 512 + 256 + j];
            float c_new = fg * c_old + ig * gg;
            float h_new = og * tanh_fast(c_new);
            g_HC[b * 512 + j]       = h_new;
            g_HC[b * 512 + 256 + j] = c_new;
            if (t == 63) sH[j] = h_new;
        }

        // final output at last step: out[b,:] = fcf([h, ctx])
        if (t == 63) {
            __syncthreads();
            if (wid < 4) {
                float acc = 0.f;
                const float* fr = &fcfw[wid * 512];
                for (int i = lane; i < 512; i += 32) {
                    float v = (i < 256) ? sH[i] : sCtx[i - 256];
                    acc += fr[i] * v;
                }
#pragma unroll
                for (int o = 16; o; o >>= 1) acc += __shfl_xor_sync(0xffffffffu, acc, o);
                if (lane == 0) out[b * 4 + wid] = acc + fcfb[wid];
            }
        }

        // ---- end-of-step: one-hop full sync on h,c ------------------------
        __syncthreads();
        if (tid == 0) flag_arrive(&g_cntH);
        flag_wait_ge(&g_cntH, tgt);
    }

    // full two-hop barrier once, then reset monotonic counters (replay-safe)
    grid_barrier();
    if (b == 0 && tid == 0) {
        asm volatile("st.relaxed.gpu.global.u32 [%0], %1;" :: "l"(&g_cntP), "r"(0u));
        asm volatile("st.relaxed.gpu.global.u32 [%0], %1;" :: "l"(&g_cntS), "r"(0u));
        asm volatile("st.relaxed.gpu.global.u32 [%0], %1;" :: "l"(&g_cntG), "r"(0u));
        asm volatile("st.relaxed.gpu.global.u32 [%0], %1;" :: "l"(&g_cntH), "r"(0u));
    }
}

// ---------------------------------------------------------------------------
extern "C" void kernel_launch(void* const* d_in, const int* in_sizes, int n_in,
                              void* d_out, int out_size) {
    const float* enc  = (const float*)d_in[0];
    const float* yh   = (const float*)d_in[1];
    const float* w1   = (const float*)d_in[2];
    const float* b1   = (const float*)d_in[3];
    const float* w2   = (const float*)d_in[4];
    const float* b2   = (const float*)d_in[5];
    const float* wih  = (const float*)d_in[6];
    const float* whh  = (const float*)d_in[7];
    const float* bih  = (const float*)d_in[8];
    const float* bhh  = (const float*)d_in[9];
    const float* fcw  = (const float*)d_in[10];
    const float* fcb  = (const float*)d_in[11];
    const float* fcfw = (const float*)d_in[12];
    const float* fcfb = (const float*)d_in[13];
    float* out = (float*)d_out;

    static int configured = 0;
    if (!configured) {
        cudaFuncSetAttribute(decoder_persistent,
                             cudaFuncAttributeMaxDynamicSharedMemorySize, SMEM_BYTES);
        configured = 1;
    }
    decoder_persistent<<<NBLK, NTHR, SMEM_BYTES>>>(
        enc, yh, w1, b1, w2, b2, wih, whh, bih, bhh, fcw, fcb, fcfw, fcfb, out);
}